// round 2
// baseline (speedup 1.0000x reference)
#include <cuda_runtime.h>

#define DEV_INLINE __device__ __forceinline__

constexpr int B_ = 8;
constexpr int C_ = 256;
constexpr int CI = 32;
constexpr int N_ = 4096;
constexpr float L2E = 1.4426950408889634f;

// Scratch (device globals: no allocation in kernel_launch).
__device__ float g_y1[B_ * CI * N_];   // 4 MB each, L2-resident
__device__ float g_y2[B_ * CI * N_];
__device__ float g_y3[B_ * CI * N_];
__device__ float g_alpha[B_ * N_];     // alpha[n] = M[n]*log2e + log2(Z[n])
__device__ float g_wT[3][C_][CI];      // w1/w2/w3 transposed to [k][co]

DEV_INLINE float fexp2(float v) { float y; asm("ex2.approx.ftz.f32 %0, %1;" : "=f"(y) : "f"(v)); return y; }
DEV_INLINE float flog2(float v) { float y; asm("lg2.approx.ftz.f32 %0, %1;" : "=f"(y) : "f"(v)); return y; }

// ---------------------------------------------------------------------------
// K0: transpose the three 32x256 conv weights into [k][co] for coalesced use.
// ---------------------------------------------------------------------------
__global__ void k0_transpose(const float* __restrict__ w1,
                             const float* __restrict__ w2,
                             const float* __restrict__ w3) {
    const float* w = blockIdx.x == 0 ? w1 : blockIdx.x == 1 ? w2 : w3;
    float* dst = &g_wT[blockIdx.x][0][0];
    for (int i = threadIdx.x; i < C_ * CI; i += blockDim.x) {
        int co = i / C_;
        int k  = i - co * C_;
        dst[k * CI + co] = w[i];
    }
}

// ---------------------------------------------------------------------------
// K1: y{1,2,3}[b][co][m] = SiLU( (w @ x)*s + bias ).
// One thread per spatial position m; 32 fp32 accumulators; w tile in smem.
// grid = (B*N/128, 3), block = 128
// ---------------------------------------------------------------------------
__global__ void __launch_bounds__(128) k1_conv(
    const float* __restrict__ x,
    const float* __restrict__ s1, const float* __restrict__ b1,
    const float* __restrict__ s2, const float* __restrict__ b2,
    const float* __restrict__ s3, const float* __restrict__ b3) {
    __shared__ float wTs[C_ * CI];  // 32 KB
    int which = blockIdx.y;
    const float* sc = which == 0 ? s1 : which == 1 ? s2 : s3;
    const float* bi = which == 0 ? b1 : which == 1 ? b2 : b3;
    float* yout = which == 0 ? g_y1 : which == 1 ? g_y2 : g_y3;
    const float* wT = &g_wT[which][0][0];
    int tid = threadIdx.x;
    for (int i = tid * 4; i < C_ * CI; i += 128 * 4)
        *(float4*)&wTs[i] = *(const float4*)&wT[i];
    __syncthreads();

    int g = blockIdx.x * 128 + tid;
    int b = g / N_;
    int m = g - b * N_;
    const float* xp = x + b * C_ * N_ + m;

    float acc[CI];
#pragma unroll
    for (int j = 0; j < CI; j++) acc[j] = 0.f;

#pragma unroll 4
    for (int k = 0; k < C_; k++) {
        float xv = __ldg(xp + k * N_);
        const float* wr = &wTs[k * CI];
#pragma unroll
        for (int j = 0; j < CI; j += 4) {
            float4 wv = *(const float4*)&wr[j];
            acc[j + 0] = fmaf(xv, wv.x, acc[j + 0]);
            acc[j + 1] = fmaf(xv, wv.y, acc[j + 1]);
            acc[j + 2] = fmaf(xv, wv.z, acc[j + 2]);
            acc[j + 3] = fmaf(xv, wv.w, acc[j + 3]);
        }
    }

    float* yp = yout + b * CI * N_ + m;
#pragma unroll
    for (int j = 0; j < CI; j++) {
        float y = fmaf(acc[j], __ldg(sc + j), __ldg(bi + j));
        float sg = 1.f / (1.f + fexp2(-y * L2E));
        yp[j * N_] = y * sg;
    }
}

// ---------------------------------------------------------------------------
// K2: per-row online softmax stats of c[n,m] = sum_k y2[k,n]*y1[k,m].
// Block: 256 thr = 16x16; block owns 64 rows n, streams all m in 64-wide
// tiles. Each thread computes a 4x4 c micro-tile (float4 LDS, 16 FFMA/k).
// grid = (N/64, B)
// ---------------------------------------------------------------------------
__global__ void __launch_bounds__(256) k2_stats() {
    __shared__ float As[CI * 64];  // y2 tile [k][n]
    __shared__ float Bs[CI * 64];  // y1 tile [k][m]
    int b = blockIdx.y;
    int n0 = blockIdx.x * 64;
    int tid = threadIdx.x;
    int tx = tid & 15, ty = tid >> 4;
    const float* y2b = g_y2 + b * CI * N_;
    const float* y1b = g_y1 + b * CI * N_;

#pragma unroll
    for (int i = tid; i < CI * 16; i += 256) {
        int k = i >> 4, c4 = (i & 15) << 2;
        *(float4*)&As[k * 64 + c4] = *(const float4*)&y2b[k * N_ + n0 + c4];
    }

    float runM[4], runL[4];
#pragma unroll
    for (int i = 0; i < 4; i++) { runM[i] = -3.0e38f; runL[i] = 0.f; }

    for (int m0 = 0; m0 < N_; m0 += 64) {
        __syncthreads();
#pragma unroll
        for (int i = tid; i < CI * 16; i += 256) {
            int k = i >> 4, c4 = (i & 15) << 2;
            *(float4*)&Bs[k * 64 + c4] = *(const float4*)&y1b[k * N_ + m0 + c4];
        }
        __syncthreads();

        float c[4][4];
#pragma unroll
        for (int i = 0; i < 4; i++)
#pragma unroll
            for (int j = 0; j < 4; j++) c[i][j] = 0.f;

#pragma unroll
        for (int k = 0; k < CI; k++) {
            float4 a  = *(const float4*)&As[k * 64 + ty * 4];
            float4 bb = *(const float4*)&Bs[k * 64 + tx * 4];
            float av[4] = {a.x, a.y, a.z, a.w};
            float bv[4] = {bb.x, bb.y, bb.z, bb.w};
#pragma unroll
            for (int i = 0; i < 4; i++)
#pragma unroll
                for (int j = 0; j < 4; j++)
                    c[i][j] = fmaf(av[i], bv[j], c[i][j]);
        }

        // online softmax update (per row, reduced across the 16 tx lanes)
#pragma unroll
        for (int i = 0; i < 4; i++) {
            float mx = fmaxf(fmaxf(c[i][0], c[i][1]), fmaxf(c[i][2], c[i][3]));
#pragma unroll
            for (int o = 1; o < 16; o <<= 1)
                mx = fmaxf(mx, __shfl_xor_sync(0xffffffffu, mx, o, 16));
            float newM = fmaxf(runM[i], mx);
            float s = fexp2((c[i][0] - newM) * L2E) + fexp2((c[i][1] - newM) * L2E)
                    + fexp2((c[i][2] - newM) * L2E) + fexp2((c[i][3] - newM) * L2E);
#pragma unroll
            for (int o = 1; o < 16; o <<= 1)
                s += __shfl_xor_sync(0xffffffffu, s, o, 16);
            runL[i] = runL[i] * fexp2((runM[i] - newM) * L2E) + s;
            runM[i] = newM;
        }
    }

    if (tx == 0) {
#pragma unroll
        for (int i = 0; i < 4; i++)
            g_alpha[b * N_ + n0 + ty * 4 + i] = fmaf(runM[i], L2E, flog2(runL[i]));
    }
}

// ---------------------------------------------------------------------------
// K3: y_last[:,m-tile] = sum_n y3[:,n] * exp2(c[n,m]*L2E - alpha[n]),
// then fused final conv (w4, s4, b4) + SiLU + residual -> out.
// Block owns a 64-wide m tile; loops n tiles: GEMM1 (c, regs) -> P (smem)
// -> GEMM2 (acc += y3 @ P). grid = (N/64, B), block 256.
// ---------------------------------------------------------------------------
__global__ void __launch_bounds__(256) k3_attn(
    const float* __restrict__ w4, const float* __restrict__ s4,
    const float* __restrict__ b4, const float* __restrict__ x,
    float* __restrict__ out) {
    __shared__ float pool[11008];  // 43 KB
    float* As  = pool;             // [32][64]  y2 n-tile
    float* Vs  = pool + 2048;      // [32][64]  y3 n-tile
    float* B1s = pool + 4096;      // [32][64]  y1 m-tile (loaded once)
    float* Ps  = pool + 6144;      // [64][68]  P tile (padded)

    int b = blockIdx.y;
    int m0 = blockIdx.x * 64;
    int tid = threadIdx.x;
    int tx = tid & 15, ty = tid >> 4;
    const float* y1b = g_y1 + b * CI * N_;
    const float* y2b = g_y2 + b * CI * N_;
    const float* y3b = g_y3 + b * CI * N_;

#pragma unroll
    for (int i = tid; i < CI * 16; i += 256) {
        int k = i >> 4, c4 = (i & 15) << 2;
        *(float4*)&B1s[k * 64 + c4] = *(const float4*)&y1b[k * N_ + m0 + c4];
    }

    float acc[2][4];
#pragma unroll
    for (int i = 0; i < 2; i++)
#pragma unroll
        for (int j = 0; j < 4; j++) acc[i][j] = 0.f;

    for (int n0 = 0; n0 < N_; n0 += 64) {
        __syncthreads();  // previous GEMM2 done (Ps/Vs reusable)
#pragma unroll
        for (int i = tid; i < CI * 16; i += 256) {
            int k = i >> 4, c4 = (i & 15) << 2;
            *(float4*)&As[k * 64 + c4] = *(const float4*)&y2b[k * N_ + n0 + c4];
            *(float4*)&Vs[k * 64 + c4] = *(const float4*)&y3b[k * N_ + n0 + c4];
        }
        __syncthreads();

        // GEMM1: c[i][j], rows n0+ty*4+i, cols m0+tx*4+j
        float c[4][4];
#pragma unroll
        for (int i = 0; i < 4; i++)
#pragma unroll
            for (int j = 0; j < 4; j++) c[i][j] = 0.f;
#pragma unroll
        for (int k = 0; k < CI; k++) {
            float4 a  = *(const float4*)&As[k * 64 + ty * 4];
            float4 bb = *(const float4*)&B1s[k * 64 + tx * 4];
            float av[4] = {a.x, a.y, a.z, a.w};
            float bv[4] = {bb.x, bb.y, bb.z, bb.w};
#pragma unroll
            for (int i = 0; i < 4; i++)
#pragma unroll
                for (int j = 0; j < 4; j++)
                    c[i][j] = fmaf(av[i], bv[j], c[i][j]);
        }

        // P = exp2(c*L2E - alpha[n]); write to smem
        float4 al = *(const float4*)&g_alpha[b * N_ + n0 + ty * 4];
        float alv[4] = {al.x, al.y, al.z, al.w};
#pragma unroll
        for (int i = 0; i < 4; i++) {
            float4 p;
            p.x = fexp2(fmaf(c[i][0], L2E, -alv[i]));
            p.y = fexp2(fmaf(c[i][1], L2E, -alv[i]));
            p.z = fexp2(fmaf(c[i][2], L2E, -alv[i]));
            p.w = fexp2(fmaf(c[i][3], L2E, -alv[i]));
            *(float4*)&Ps[(ty * 4 + i) * 68 + tx * 4] = p;
        }
        __syncthreads();

        // GEMM2: acc[ci=ty*2+i][m=tx*4+j] += sum_nn Vs[ci][nn]*Ps[nn][m]
#pragma unroll 8
        for (int nn = 0; nn < 64; ++nn) {
            float v0 = Vs[(ty * 2 + 0) * 64 + nn];
            float v1 = Vs[(ty * 2 + 1) * 64 + nn];
            float4 p4 = *(const float4*)&Ps[nn * 68 + tx * 4];
            acc[0][0] = fmaf(v0, p4.x, acc[0][0]);
            acc[0][1] = fmaf(v0, p4.y, acc[0][1]);
            acc[0][2] = fmaf(v0, p4.z, acc[0][2]);
            acc[0][3] = fmaf(v0, p4.w, acc[0][3]);
            acc[1][0] = fmaf(v1, p4.x, acc[1][0]);
            acc[1][1] = fmaf(v1, p4.y, acc[1][1]);
            acc[1][2] = fmaf(v1, p4.z, acc[1][2]);
            acc[1][3] = fmaf(v1, p4.w, acc[1][3]);
        }
    }

    // ---- fused epilogue: final conv + BN + SiLU + residual ----
    __syncthreads();
    float* Ys  = pool;           // [32][68] y_last tile
    float* W4s = pool + 2304;    // [256][32]
    float* s4s = pool + 10496;   // [256]
    float* b4s = pool + 10752;   // [256]

#pragma unroll
    for (int i = 0; i < 2; i++)
#pragma unroll
        for (int j = 0; j < 4; j++)
            Ys[(ty * 2 + i) * 68 + tx * 4 + j] = acc[i][j];
    for (int i = tid; i < C_ * CI; i += 256) W4s[i] = w4[i];
    s4s[tid] = s4[tid];
    b4s[tid] = b4[tid];
    __syncthreads();

    int m = tid & 63;
    int cg = tid >> 6;  // 0..3 -> 64 output channels each
    float yv[CI];
#pragma unroll
    for (int ci = 0; ci < CI; ci++) yv[ci] = Ys[ci * 68 + m];

    const float* xb = x + b * C_ * N_ + m0 + m;
    float* ob = out + b * C_ * N_ + m0 + m;
#pragma unroll 4
    for (int co = cg * 64; co < (cg + 1) * 64; ++co) {
        float s = 0.f;
#pragma unroll
        for (int c4 = 0; c4 < CI; c4 += 4) {
            float4 wv = *(const float4*)&W4s[co * CI + c4];
            s = fmaf(wv.x, yv[c4 + 0], s);
            s = fmaf(wv.y, yv[c4 + 1], s);
            s = fmaf(wv.z, yv[c4 + 2], s);
            s = fmaf(wv.w, yv[c4 + 3], s);
        }
        float yy = fmaf(s, s4s[co], b4s[co]);
        float sg = 1.f / (1.f + fexp2(-yy * L2E));
        ob[co * N_] = fmaf(yy, sg, __ldg(xb + co * N_));
    }
}

// ---------------------------------------------------------------------------
extern "C" void kernel_launch(void* const* d_in, const int* in_sizes, int n_in,
                              void* d_out, int out_size) {
    (void)in_sizes; (void)n_in; (void)out_size;
    const float* x  = (const float*)d_in[0];
    const float* w1 = (const float*)d_in[1];
    const float* s1 = (const float*)d_in[2];
    const float* b1 = (const float*)d_in[3];
    const float* w2 = (const float*)d_in[4];
    const float* s2 = (const float*)d_in[5];
    const float* b2 = (const float*)d_in[6];
    const float* w3 = (const float*)d_in[7];
    const float* s3 = (const float*)d_in[8];
    const float* b3 = (const float*)d_in[9];
    const float* w4 = (const float*)d_in[10];
    const float* s4 = (const float*)d_in[11];
    const float* b4 = (const float*)d_in[12];
    float* out = (float*)d_out;

    k0_transpose<<<3, 256>>>(w1, w2, w3);
    k1_conv<<<dim3(B_ * N_ / 128, 3), 128>>>(x, s1, b1, s2, b2, s3, b3);
    k2_stats<<<dim3(N_ / 64, B_), 256>>>();
    k3_attn<<<dim3(N_ / 64, B_), 256>>>(w4, s4, b4, x, out);
}

// round 3
// speedup vs baseline: 1.1518x; 1.1518x over previous
#include <cuda_runtime.h>

#define DEV_INLINE __device__ __forceinline__
typedef unsigned long long u64;

constexpr int B_ = 8;
constexpr int C_ = 256;
constexpr int CI = 32;
constexpr int N_ = 4096;
constexpr float L2E = 1.4426950408889634f;
constexpr int PSS = 132;  // Ps row stride (floats)

// Scratch (device globals: no allocation anywhere).
__device__ __align__(128) float g_y1[B_ * CI * N_];
__device__ __align__(128) float g_y2[B_ * CI * N_];   // pre-scaled by log2(e)
__device__ __align__(128) float g_y3[B_ * CI * N_];
__device__ __align__(128) float g_alpha[B_ * N_];     // log2 domain: M + log2(Z)
__device__ __align__(128) float g_wAll[C_ * 96];      // [k][br*32+co]

DEV_INLINE float fexp2(float v) { float y; asm("ex2.approx.ftz.f32 %0, %1;" : "=f"(y) : "f"(v)); return y; }
DEV_INLINE float flog2(float v) { float y; asm("lg2.approx.ftz.f32 %0, %1;" : "=f"(y) : "f"(v)); return y; }
DEV_INLINE float frcp(float v)  { float y; asm("rcp.approx.ftz.f32 %0, %1;" : "=f"(y) : "f"(v)); return y; }

DEV_INLINE u64 pack2(float lo, float hi) {
    u64 r;
    asm("mov.b64 %0, {%1,%2};" : "=l"(r)
        : "r"(__float_as_uint(lo)), "r"(__float_as_uint(hi)));
    return r;
}
DEV_INLINE void unpack2(u64 v, float& lo, float& hi) {
    unsigned a, b;
    asm("mov.b64 {%0,%1}, %2;" : "=r"(a), "=r"(b) : "l"(v));
    lo = __uint_as_float(a); hi = __uint_as_float(b);
}
DEV_INLINE u64 fma2(u64 a, u64 b, u64 c) {   // packed f32x2 FMA (sm_103a)
    u64 d;
    asm("fma.rn.f32x2 %0, %1, %2, %3;" : "=l"(d) : "l"(a), "l"(b), "l"(c));
    return d;
}

// ---- [32][128] fp32 tile movers -------------------------------------------
DEV_INLINE void ldt(const float* __restrict__ src, int col0, float4 pre[4], int tid) {
#pragma unroll
    for (int s = 0; s < 4; s++) {
        int idx = tid + s * 256;                 // float4 index 0..1023
        int k = idx >> 5, off = (idx & 31) << 2;
        pre[s] = *(const float4*)&src[k * N_ + col0 + off];
    }
}
DEV_INLINE void stt(float* dst, const float4 pre[4], int tid) {
#pragma unroll
    for (int s = 0; s < 4; s++)
        *(float4*)&dst[(tid + s * 256) << 2] = pre[s];   // [k][128]
}
DEV_INLINE void stt_dup(float2* dst, const float4 pre[4], int tid) {
#pragma unroll
    for (int s = 0; s < 4; s++) {
        int idx = tid + s * 256;
        int base = (idx >> 5) * 128 + ((idx & 31) << 2);
        float v[4] = {pre[s].x, pre[s].y, pre[s].z, pre[s].w};
#pragma unroll
        for (int j = 0; j < 4; j++) dst[base + j] = make_float2(v[j], v[j]);
    }
}

// ---- GEMM1 micro-kernel: c[8 rows][8 cols as 4 pairs], K=32 -----------------
// Ad: duplicated A [k][128] float2 (rows, broadcast); Bs: [k][128] (cols).
DEV_INLINE void gemm1(const float2* __restrict__ Ad, const float* __restrict__ Bs,
                      int ty, int tx, u64 c2[8][4]) {
#pragma unroll 4
    for (int k = 0; k < CI; k++) {
        ulonglong2 B0 = *(const ulonglong2*)&Bs[k * 128 + tx * 8];
        ulonglong2 B1 = *(const ulonglong2*)&Bs[k * 128 + tx * 8 + 4];
#pragma unroll
        for (int i = 0; i < 8; i++) {
            u64 a = *(const u64*)&Ad[k * 128 + ty * 8 + i];
            c2[i][0] = fma2(a, B0.x, c2[i][0]);
            c2[i][1] = fma2(a, B0.y, c2[i][1]);
            c2[i][2] = fma2(a, B1.x, c2[i][2]);
            c2[i][3] = fma2(a, B1.y, c2[i][3]);
        }
    }
}

// ---------------------------------------------------------------------------
// K0: pack w1/w2/w3 ([co][k]) into g_wAll[k][br*32+co].
// ---------------------------------------------------------------------------
__global__ void k0_prep(const float* __restrict__ w1, const float* __restrict__ w2,
                        const float* __restrict__ w3) {
    int i = blockIdx.x * 256 + threadIdx.x;
    if (i < C_ * 96) {
        int k = i / 96, j = i - k * 96;
        int br = j >> 5, co = j & 31;
        const float* w = br == 0 ? w1 : br == 1 ? w2 : w3;
        g_wAll[i] = w[co * C_ + k];
    }
}

// ---------------------------------------------------------------------------
// K1: all three branch convs fused. One thread per position; 48 f32x2 accs.
// grid = 128, block = 256, dyn smem = 99072 B
// ---------------------------------------------------------------------------
__global__ void __launch_bounds__(256, 1) k1_conv(
    const float* __restrict__ x,
    const float* __restrict__ s1, const float* __restrict__ b1,
    const float* __restrict__ s2, const float* __restrict__ b2,
    const float* __restrict__ s3, const float* __restrict__ b3) {
    extern __shared__ float sm[];
    float* wAll = sm;             // [256][96]
    float* sAll = sm + 24576;     // 96
    float* bAll = sAll + 96;
    int tid = threadIdx.x;
    const float4* wsrc = (const float4*)g_wAll;
#pragma unroll
    for (int s = 0; s < 24; s++) ((float4*)wAll)[tid + s * 256] = wsrc[tid + s * 256];
    if (tid < 96) {
        sAll[tid] = tid < 32 ? s1[tid] : tid < 64 ? s2[tid - 32] : s3[tid - 64];
        bAll[tid] = tid < 32 ? b1[tid] : tid < 64 ? b2[tid - 32] : b3[tid - 64];
    }
    __syncthreads();

    int gpos = blockIdx.x * 256 + tid;
    int b = gpos >> 12, m = gpos & (N_ - 1);
    const float* xp = x + b * C_ * N_ + m;

    u64 acc2[48];
#pragma unroll
    for (int i = 0; i < 48; i++) acc2[i] = 0ull;

#pragma unroll 2
    for (int k = 0; k < C_; k++) {
        float xv = __ldg(&xp[k * N_]);
        u64 xq = pack2(xv, xv);
        const ulonglong2* wk = (const ulonglong2*)&wAll[k * 96];
#pragma unroll
        for (int t = 0; t < 24; t++) {
            ulonglong2 wv = wk[t];
            acc2[2 * t]     = fma2(xq, wv.x, acc2[2 * t]);
            acc2[2 * t + 1] = fma2(xq, wv.y, acc2[2 * t + 1]);
        }
    }

    float* outs[3] = {g_y1, g_y2, g_y3};
#pragma unroll
    for (int br = 0; br < 3; br++) {
        float* op = outs[br] + b * CI * N_ + m;
        float mulf = (br == 1) ? L2E : 1.f;
#pragma unroll
        for (int p = 0; p < 16; p++) {
            int co = 2 * p;
            float v0, v1;
            unpack2(acc2[br * 16 + p], v0, v1);
            float y0 = fmaf(v0, sAll[br * 32 + co],     bAll[br * 32 + co]);
            float y1 = fmaf(v1, sAll[br * 32 + co + 1], bAll[br * 32 + co + 1]);
            op[co * N_]       = y0 * frcp(1.f + fexp2(-y0 * L2E)) * mulf;
            op[(co + 1) * N_] = y1 * frcp(1.f + fexp2(-y1 * L2E)) * mulf;
        }
    }
}

// ---------------------------------------------------------------------------
// K2: per-row softmax stats (log2 domain), per-lane online accumulation,
// single cross-lane merge at the end. grid = (32, 8), block = 256,
// dyn smem = 49152 B.
// ---------------------------------------------------------------------------
__global__ void __launch_bounds__(256, 1) k2_stats() {
    extern __shared__ float sm[];
    float2* Ad = (float2*)sm;     // 32 KB duplicated y2 tile [32][128]
    float* Bs  = sm + 8192;       // 16 KB y1 tile [32][128]
    int b = blockIdx.y, n0 = blockIdx.x * 128;
    int tid = threadIdx.x, tx = tid & 15, ty = tid >> 4;
    const float* y2b = g_y2 + b * CI * N_;
    const float* y1b = g_y1 + b * CI * N_;

    float4 pre[4];
    ldt(y2b, n0, pre, tid); stt_dup(Ad, pre, tid);
    ldt(y1b, 0, pre, tid);  stt(Bs, pre, tid);
    __syncthreads();

    float runM[8], runL[8];
#pragma unroll
    for (int i = 0; i < 8; i++) { runM[i] = -1.0e30f; runL[i] = 0.f; }

    for (int t = 0; t < N_ / 128; t++) {
        bool more = (t + 1 < N_ / 128);
        if (more) ldt(y1b, (t + 1) * 128, pre, tid);

        u64 c2[8][4];
#pragma unroll
        for (int i = 0; i < 8; i++)
#pragma unroll
            for (int j = 0; j < 4; j++) c2[i][j] = 0ull;
        gemm1(Ad, Bs, ty, tx, c2);

#pragma unroll
        for (int i = 0; i < 8; i++) {
            float e[8];
            unpack2(c2[i][0], e[0], e[1]); unpack2(c2[i][1], e[2], e[3]);
            unpack2(c2[i][2], e[4], e[5]); unpack2(c2[i][3], e[6], e[7]);
            float mx = fmaxf(fmaxf(fmaxf(e[0], e[1]), fmaxf(e[2], e[3])),
                             fmaxf(fmaxf(e[4], e[5]), fmaxf(e[6], e[7])));
            float nM = fmaxf(runM[i], mx);
            float s = ((fexp2(e[0] - nM) + fexp2(e[1] - nM)) + (fexp2(e[2] - nM) + fexp2(e[3] - nM)))
                    + ((fexp2(e[4] - nM) + fexp2(e[5] - nM)) + (fexp2(e[6] - nM) + fexp2(e[7] - nM)));
            runL[i] = fmaf(runL[i], fexp2(runM[i] - nM), s);
            runM[i] = nM;
        }
        __syncthreads();
        if (more) { stt(Bs, pre, tid); }
        __syncthreads();
    }

#pragma unroll
    for (int i = 0; i < 8; i++) {
        float M = runM[i], Z = runL[i];
#pragma unroll
        for (int off = 1; off < 16; off <<= 1) {
            float Mo = __shfl_xor_sync(0xffffffffu, M, off, 16);
            float Zo = __shfl_xor_sync(0xffffffffu, Z, off, 16);
            float nM = fmaxf(M, Mo);
            Z = fmaf(Z, fexp2(M - nM), Zo * fexp2(Mo - nM));
            M = nM;
        }
        if (tx == 0) g_alpha[b * N_ + n0 + ty * 8 + i] = M + flog2(Z);
    }
}

// ---------------------------------------------------------------------------
// K3: y_last + fused final conv + SiLU + residual.
// grid = (32, 8), block = 256, dyn smem = 149504 B.
// ---------------------------------------------------------------------------
__global__ void __launch_bounds__(256, 1) k3_attn(
    const float* __restrict__ w4, const float* __restrict__ s4,
    const float* __restrict__ b4, const float* __restrict__ x,
    float* __restrict__ out) {
    extern __shared__ float sm[];
    float2* Ad = (float2*)sm;            // floats [0, 8192)    : dup y2 tile
    float2* Vd = (float2*)(sm + 8192);   // floats [8192,16384) : dup y3 tile
    float* B1s = sm + 16384;             // floats [16384,20480): y1 m-tile
    float* Ps  = sm + 20480;             // floats [20480,37376): [128][132]

    int b = blockIdx.y, m0 = blockIdx.x * 128;
    int tid = threadIdx.x, tx = tid & 15, ty = tid >> 4;
    int w = tid >> 5, lane = tid & 31;
    int ciBase = (w & 1) * 16 + (lane >> 3) * 4;
    int mbase  = (w >> 1) * 32 + (lane & 7) * 4;
    const float* y1b = g_y1 + b * CI * N_;
    const float* y2b = g_y2 + b * CI * N_;
    const float* y3b = g_y3 + b * CI * N_;
    const float* alb = g_alpha + b * N_;

    float4 pre[4], preV[4];
    ldt(y1b, m0, pre, tid); stt(B1s, pre, tid);
    ldt(y2b, 0, pre, tid);  stt_dup(Ad, pre, tid);
    ldt(y3b, 0, preV, tid); stt_dup(Vd, preV, tid);
    __syncthreads();

    u64 acc2[4][2];
#pragma unroll
    for (int i = 0; i < 4; i++) { acc2[i][0] = 0ull; acc2[i][1] = 0ull; }

    for (int t = 0; t < N_ / 128; t++) {
        int n0 = t * 128;
        bool more = (t + 1 < N_ / 128);
        if (more) { ldt(y2b, n0 + 128, pre, tid); ldt(y3b, n0 + 128, preV, tid); }

        float4 a0 = *(const float4*)&alb[n0 + ty * 8];
        float4 a1 = *(const float4*)&alb[n0 + ty * 8 + 4];
        float al[8] = {a0.x, a0.y, a0.z, a0.w, a1.x, a1.y, a1.z, a1.w};

        u64 c2[8][4];
#pragma unroll
        for (int i = 0; i < 8; i++)
#pragma unroll
            for (int j = 0; j < 4; j++) c2[i][j] = 0ull;
        gemm1(Ad, B1s, ty, tx, c2);

#pragma unroll
        for (int i = 0; i < 8; i++) {
            float e[8];
            unpack2(c2[i][0], e[0], e[1]); unpack2(c2[i][1], e[2], e[3]);
            unpack2(c2[i][2], e[4], e[5]); unpack2(c2[i][3], e[6], e[7]);
            float4 p0, p1;
            p0.x = fexp2(e[0] - al[i]); p0.y = fexp2(e[1] - al[i]);
            p0.z = fexp2(e[2] - al[i]); p0.w = fexp2(e[3] - al[i]);
            p1.x = fexp2(e[4] - al[i]); p1.y = fexp2(e[5] - al[i]);
            p1.z = fexp2(e[6] - al[i]); p1.w = fexp2(e[7] - al[i]);
            *(float4*)&Ps[(ty * 8 + i) * PSS + tx * 8]     = p0;
            *(float4*)&Ps[(ty * 8 + i) * PSS + tx * 8 + 4] = p1;
        }
        __syncthreads();

#pragma unroll 4
        for (int nn = 0; nn < 128; nn++) {
            ulonglong2 pv = *(const ulonglong2*)&Ps[nn * PSS + mbase];
#pragma unroll
            for (int i = 0; i < 4; i++) {
                u64 v = *(const u64*)&Vd[(ciBase + i) * 128 + nn];
                acc2[i][0] = fma2(v, pv.x, acc2[i][0]);
                acc2[i][1] = fma2(v, pv.y, acc2[i][1]);
            }
        }
        __syncthreads();
        if (more) {
            stt_dup(Ad, pre, tid); stt_dup(Vd, preV, tid);
            __syncthreads();
        }
    }

    // ---- fused epilogue: final conv + BN + SiLU + residual ----
    float* Ys   = sm;                    // [32][132] floats
    float2* W4d = (float2*)(sm + 8192);  // [32][256] dup
    float* s4s  = sm + 24576;
    float* b4s  = sm + 24832;

#pragma unroll
    for (int i = 0; i < 4; i++)
#pragma unroll
        for (int j = 0; j < 2; j++)
            *(u64*)&Ys[(ciBase + i) * PSS + mbase + 2 * j] = acc2[i][j];
    for (int idx = tid; idx < C_ * CI; idx += 256) {
        int k = idx & 31, co = idx >> 5;
        float v = w4[co * CI + k];
        W4d[k * 256 + co] = make_float2(v, v);
    }
    s4s[tid] = s4[tid];
    b4s[tid] = b4[tid];
    __syncthreads();

    int mg = tid & 7, cog = tid >> 3;
    int co0 = cog * 8;
#pragma unroll
    for (int pass = 0; pass < 2; pass++) {
        int cp = co0 + pass * 4;
        u64 e2[4][8];
#pragma unroll
        for (int i = 0; i < 4; i++)
#pragma unroll
            for (int j = 0; j < 8; j++) e2[i][j] = 0ull;
#pragma unroll 4
        for (int k = 0; k < CI; k++) {
            u64 yv[8];
#pragma unroll
            for (int j = 0; j < 8; j++)
                yv[j] = *(const u64*)&Ys[k * PSS + 2 * (mg + 8 * j)];
#pragma unroll
            for (int i = 0; i < 4; i++) {
                u64 wv = *(const u64*)&W4d[k * 256 + cp + i];
#pragma unroll
                for (int j = 0; j < 8; j++) e2[i][j] = fma2(wv, yv[j], e2[i][j]);
            }
        }
#pragma unroll
        for (int i = 0; i < 4; i++) {
            float sc = s4s[cp + i], bi = b4s[cp + i];
            int rowoff = b * C_ * N_ + (cp + i) * N_ + m0;
#pragma unroll
            for (int j = 0; j < 8; j++) {
                float v0, v1;
                unpack2(e2[i][j], v0, v1);
                float y0 = fmaf(v0, sc, bi), y1 = fmaf(v1, sc, bi);
                float o0 = y0 * frcp(1.f + fexp2(-y0 * L2E));
                float o1 = y1 * frcp(1.f + fexp2(-y1 * L2E));
                int m = 2 * (mg + 8 * j);
                float2 xr = *(const float2*)&x[rowoff + m];
                float2 ov = make_float2(o0 + xr.x, o1 + xr.y);
                *(float2*)&out[rowoff + m] = ov;
            }
        }
    }
}

// ---------------------------------------------------------------------------
extern "C" void kernel_launch(void* const* d_in, const int* in_sizes, int n_in,
                              void* d_out, int out_size) {
    (void)in_sizes; (void)n_in; (void)out_size;
    const float* x  = (const float*)d_in[0];
    const float* w1 = (const float*)d_in[1];
    const float* s1 = (const float*)d_in[2];
    const float* b1 = (const float*)d_in[3];
    const float* w2 = (const float*)d_in[4];
    const float* s2 = (const float*)d_in[5];
    const float* b2 = (const float*)d_in[6];
    const float* w3 = (const float*)d_in[7];
    const float* s3 = (const float*)d_in[8];
    const float* b3 = (const float*)d_in[9];
    const float* w4 = (const float*)d_in[10];
    const float* s4 = (const float*)d_in[11];
    const float* b4 = (const float*)d_in[12];
    float* out = (float*)d_out;

    cudaFuncSetAttribute(k1_conv, cudaFuncAttributeMaxDynamicSharedMemorySize, 99072);
    cudaFuncSetAttribute(k2_stats, cudaFuncAttributeMaxDynamicSharedMemorySize, 49152);
    cudaFuncSetAttribute(k3_attn, cudaFuncAttributeMaxDynamicSharedMemorySize, 149504);

    k0_prep<<<96, 256>>>(w1, w2, w3);
    k1_conv<<<128, 256, 99072>>>(x, s1, b1, s2, b2, s3, b3);
    k2_stats<<<dim3(32, B_), 256, 49152>>>();
    k3_attn<<<dim3(32, B_), 256, 149504>>>(w4, s4, b4, x, out);
}

// round 4
// speedup vs baseline: 1.1598x; 1.0070x over previous
#include <cuda_runtime.h>

#define DEV_INLINE __device__ __forceinline__
typedef unsigned long long u64;

constexpr int B_ = 8;
constexpr int C_ = 256;
constexpr int CI = 32;
constexpr int N_ = 4096;
constexpr float L2E = 1.4426950408889634f;
constexpr int PSS = 132;  // Ps row stride (floats)

// Scratch (device globals: no allocation anywhere).
__device__ __align__(128) float g_y1[B_ * CI * N_];
__device__ __align__(128) float g_y2[B_ * CI * N_];   // pre-scaled by log2(e)
__device__ __align__(128) float g_y3[B_ * CI * N_];
__device__ __align__(128) float g_alpha[B_ * N_];     // log2 domain: M + log2(Z)
__device__ __align__(128) float g_wAll[C_ * 96];      // [k][br*32+co]

DEV_INLINE float fexp2(float v) { float y; asm("ex2.approx.ftz.f32 %0, %1;" : "=f"(y) : "f"(v)); return y; }
DEV_INLINE float flog2(float v) { float y; asm("lg2.approx.ftz.f32 %0, %1;" : "=f"(y) : "f"(v)); return y; }
DEV_INLINE float frcp(float v)  { float y; asm("rcp.approx.ftz.f32 %0, %1;" : "=f"(y) : "f"(v)); return y; }

DEV_INLINE u64 pack2(float lo, float hi) {
    u64 r;
    asm("mov.b64 %0, {%1,%2};" : "=l"(r)
        : "r"(__float_as_uint(lo)), "r"(__float_as_uint(hi)));
    return r;
}
DEV_INLINE void unpack2(u64 v, float& lo, float& hi) {
    unsigned a, b;
    asm("mov.b64 {%0,%1}, %2;" : "=r"(a), "=r"(b) : "l"(v));
    lo = __uint_as_float(a); hi = __uint_as_float(b);
}
DEV_INLINE u64 fma2(u64 a, u64 b, u64 c) {   // packed f32x2 FMA (sm_103a)
    u64 d;
    asm("fma.rn.f32x2 %0, %1, %2, %3;" : "=l"(d) : "l"(a), "l"(b), "l"(c));
    return d;
}

// ---- [32][128] fp32 tile movers -------------------------------------------
DEV_INLINE void ldt(const float* __restrict__ src, int col0, float4 pre[4], int tid) {
#pragma unroll
    for (int s = 0; s < 4; s++) {
        int idx = tid + s * 256;                 // float4 index 0..1023
        int k = idx >> 5, off = (idx & 31) << 2;
        pre[s] = *(const float4*)&src[k * N_ + col0 + off];
    }
}
DEV_INLINE void stt(float* dst, const float4 pre[4], int tid) {
#pragma unroll
    for (int s = 0; s < 4; s++)
        *(float4*)&dst[(tid + s * 256) << 2] = pre[s];   // [k][128]
}
DEV_INLINE void stt_dup(float2* dst, const float4 pre[4], int tid) {
#pragma unroll
    for (int s = 0; s < 4; s++) {
        int idx = tid + s * 256;
        int base = (idx >> 5) * 128 + ((idx & 31) << 2);
        float v[4] = {pre[s].x, pre[s].y, pre[s].z, pre[s].w};
#pragma unroll
        for (int j = 0; j < 4; j++) dst[base + j] = make_float2(v[j], v[j]);
    }
}

// ---- GEMM1 micro-kernel: c[8 rows][8 cols as 4 pairs], K=32 -----------------
// Ad: duplicated A [k][128] float2 (rows, broadcast); Bs: [k][128] (cols).
DEV_INLINE void gemm1(const float2* __restrict__ Ad, const float* __restrict__ Bs,
                      int ty, int tx, u64 c2[8][4]) {
#pragma unroll 4
    for (int k = 0; k < CI; k++) {
        ulonglong2 B0 = *(const ulonglong2*)&Bs[k * 128 + tx * 8];
        ulonglong2 B1 = *(const ulonglong2*)&Bs[k * 128 + tx * 8 + 4];
#pragma unroll
        for (int i = 0; i < 8; i++) {
            u64 a = *(const u64*)&Ad[k * 128 + ty * 8 + i];
            c2[i][0] = fma2(a, B0.x, c2[i][0]);
            c2[i][1] = fma2(a, B0.y, c2[i][1]);
            c2[i][2] = fma2(a, B1.x, c2[i][2]);
            c2[i][3] = fma2(a, B1.y, c2[i][3]);
        }
    }
}

// ---------------------------------------------------------------------------
// K0: pack w1/w2/w3 ([co][k]) into g_wAll[k][br*32+co].
// ---------------------------------------------------------------------------
__global__ void k0_prep(const float* __restrict__ w1, const float* __restrict__ w2,
                        const float* __restrict__ w3) {
    int i = blockIdx.x * 256 + threadIdx.x;
    if (i < C_ * 96) {
        int k = i / 96, j = i - k * 96;
        int br = j >> 5, co = j & 31;
        const float* w = br == 0 ? w1 : br == 1 ? w2 : w3;
        g_wAll[i] = w[co * C_ + k];
    }
}

// ---------------------------------------------------------------------------
// K1: all three branch convs fused. One thread per position; 48 f32x2 accs.
// grid = 128, block = 256, dyn smem = 99072 B
// ---------------------------------------------------------------------------
__global__ void __launch_bounds__(256, 1) k1_conv(
    const float* __restrict__ x,
    const float* __restrict__ s1, const float* __restrict__ b1,
    const float* __restrict__ s2, const float* __restrict__ b2,
    const float* __restrict__ s3, const float* __restrict__ b3) {
    extern __shared__ float sm[];
    float* wAll = sm;             // [256][96]
    float* sAll = sm + 24576;     // 96
    float* bAll = sAll + 96;
    int tid = threadIdx.x;
    const float4* wsrc = (const float4*)g_wAll;
#pragma unroll
    for (int s = 0; s < 24; s++) ((float4*)wAll)[tid + s * 256] = wsrc[tid + s * 256];
    if (tid < 96) {
        sAll[tid] = tid < 32 ? s1[tid] : tid < 64 ? s2[tid - 32] : s3[tid - 64];
        bAll[tid] = tid < 32 ? b1[tid] : tid < 64 ? b2[tid - 32] : b3[tid - 64];
    }
    __syncthreads();

    int gpos = blockIdx.x * 256 + tid;
    int b = gpos >> 12, m = gpos & (N_ - 1);
    const float* xp = x + b * C_ * N_ + m;

    u64 acc2[48];
#pragma unroll
    for (int i = 0; i < 48; i++) acc2[i] = 0ull;

#pragma unroll 2
    for (int k = 0; k < C_; k++) {
        float xv = __ldg(&xp[k * N_]);
        u64 xq = pack2(xv, xv);
        const ulonglong2* wk = (const ulonglong2*)&wAll[k * 96];
#pragma unroll
        for (int t = 0; t < 24; t++) {
            ulonglong2 wv = wk[t];
            acc2[2 * t]     = fma2(xq, wv.x, acc2[2 * t]);
            acc2[2 * t + 1] = fma2(xq, wv.y, acc2[2 * t + 1]);
        }
    }

    float* outs[3] = {g_y1, g_y2, g_y3};
#pragma unroll
    for (int br = 0; br < 3; br++) {
        float* op = outs[br] + b * CI * N_ + m;
        float mulf = (br == 1) ? L2E : 1.f;
#pragma unroll
        for (int p = 0; p < 16; p++) {
            int co = 2 * p;
            float v0, v1;
            unpack2(acc2[br * 16 + p], v0, v1);
            float y0 = fmaf(v0, sAll[br * 32 + co],     bAll[br * 32 + co]);
            float y1 = fmaf(v1, sAll[br * 32 + co + 1], bAll[br * 32 + co + 1]);
            op[co * N_]       = y0 * frcp(1.f + fexp2(-y0 * L2E)) * mulf;
            op[(co + 1) * N_] = y1 * frcp(1.f + fexp2(-y1 * L2E)) * mulf;
        }
    }
}

// ---------------------------------------------------------------------------
// K2: per-row softmax stats (log2 domain), per-lane online accumulation,
// single cross-lane merge at the end. grid = (32, 8), block = 256,
// dyn smem = 49152 B.
// ---------------------------------------------------------------------------
__global__ void __launch_bounds__(256, 1) k2_stats() {
    extern __shared__ float sm[];
    float2* Ad = (float2*)sm;     // 32 KB duplicated y2 tile [32][128]
    float* Bs  = sm + 8192;       // 16 KB y1 tile [32][128]
    int b = blockIdx.y, n0 = blockIdx.x * 128;
    int tid = threadIdx.x, tx = tid & 15, ty = tid >> 4;
    const float* y2b = g_y2 + b * CI * N_;
    const float* y1b = g_y1 + b * CI * N_;

    float4 pre[4];
    ldt(y2b, n0, pre, tid); stt_dup(Ad, pre, tid);
    ldt(y1b, 0, pre, tid);  stt(Bs, pre, tid);
    __syncthreads();

    float runM[8], runL[8];
#pragma unroll
    for (int i = 0; i < 8; i++) { runM[i] = -1.0e30f; runL[i] = 0.f; }

    for (int t = 0; t < N_ / 128; t++) {
        bool more = (t + 1 < N_ / 128);
        if (more) ldt(y1b, (t + 1) * 128, pre, tid);

        u64 c2[8][4];
#pragma unroll
        for (int i = 0; i < 8; i++)
#pragma unroll
            for (int j = 0; j < 4; j++) c2[i][j] = 0ull;
        gemm1(Ad, Bs, ty, tx, c2);

#pragma unroll
        for (int i = 0; i < 8; i++) {
            float e[8];
            unpack2(c2[i][0], e[0], e[1]); unpack2(c2[i][1], e[2], e[3]);
            unpack2(c2[i][2], e[4], e[5]); unpack2(c2[i][3], e[6], e[7]);
            float mx = fmaxf(fmaxf(fmaxf(e[0], e[1]), fmaxf(e[2], e[3])),
                             fmaxf(fmaxf(e[4], e[5]), fmaxf(e[6], e[7])));
            float nM = fmaxf(runM[i], mx);
            float s = ((fexp2(e[0] - nM) + fexp2(e[1] - nM)) + (fexp2(e[2] - nM) + fexp2(e[3] - nM)))
                    + ((fexp2(e[4] - nM) + fexp2(e[5] - nM)) + (fexp2(e[6] - nM) + fexp2(e[7] - nM)));
            runL[i] = fmaf(runL[i], fexp2(runM[i] - nM), s);
            runM[i] = nM;
        }
        __syncthreads();
        if (more) { stt(Bs, pre, tid); }
        __syncthreads();
    }

#pragma unroll
    for (int i = 0; i < 8; i++) {
        float M = runM[i], Z = runL[i];
#pragma unroll
        for (int off = 1; off < 16; off <<= 1) {
            float Mo = __shfl_xor_sync(0xffffffffu, M, off, 16);
            float Zo = __shfl_xor_sync(0xffffffffu, Z, off, 16);
            float nM = fmaxf(M, Mo);
            Z = fmaf(Z, fexp2(M - nM), Zo * fexp2(Mo - nM));
            M = nM;
        }
        if (tx == 0) g_alpha[b * N_ + n0 + ty * 8 + i] = M + flog2(Z);
    }
}

// ---------------------------------------------------------------------------
// K3: y_last + fused final conv + SiLU + residual.
// grid = (32, 8), block = 256, dyn smem = 149504 B.
// ---------------------------------------------------------------------------
__global__ void __launch_bounds__(256, 1) k3_attn(
    const float* __restrict__ w4, const float* __restrict__ s4,
    const float* __restrict__ b4, const float* __restrict__ x,
    float* __restrict__ out) {
    extern __shared__ float sm[];
    float2* Ad = (float2*)sm;            // floats [0, 8192)    : dup y2 tile
    float2* Vd = (float2*)(sm + 8192);   // floats [8192,16384) : dup y3 tile
    float* B1s = sm + 16384;             // floats [16384,20480): y1 m-tile
    float* Ps  = sm + 20480;             // floats [20480,37376): [128][132]

    int b = blockIdx.y, m0 = blockIdx.x * 128;
    int tid = threadIdx.x, tx = tid & 15, ty = tid >> 4;
    int w = tid >> 5, lane = tid & 31;
    int ciBase = (w & 1) * 16 + (lane >> 3) * 4;
    int mbase  = (w >> 1) * 32 + (lane & 7) * 4;
    const float* y1b = g_y1 + b * CI * N_;
    const float* y2b = g_y2 + b * CI * N_;
    const float* y3b = g_y3 + b * CI * N_;
    const float* alb = g_alpha + b * N_;

    float4 pre[4], preV[4];
    ldt(y1b, m0, pre, tid); stt(B1s, pre, tid);
    ldt(y2b, 0, pre, tid);  stt_dup(Ad, pre, tid);
    ldt(y3b, 0, preV, tid); stt_dup(Vd, preV, tid);
    __syncthreads();

    u64 acc2[4][2];
#pragma unroll
    for (int i = 0; i < 4; i++) { acc2[i][0] = 0ull; acc2[i][1] = 0ull; }

    for (int t = 0; t < N_ / 128; t++) {
        int n0 = t * 128;
        bool more = (t + 1 < N_ / 128);
        if (more) { ldt(y2b, n0 + 128, pre, tid); ldt(y3b, n0 + 128, preV, tid); }

        float4 a0 = *(const float4*)&alb[n0 + ty * 8];
        float4 a1 = *(const float4*)&alb[n0 + ty * 8 + 4];
        float al[8] = {a0.x, a0.y, a0.z, a0.w, a1.x, a1.y, a1.z, a1.w};

        u64 c2[8][4];
#pragma unroll
        for (int i = 0; i < 8; i++)
#pragma unroll
            for (int j = 0; j < 4; j++) c2[i][j] = 0ull;
        gemm1(Ad, B1s, ty, tx, c2);

#pragma unroll
        for (int i = 0; i < 8; i++) {
            float e[8];
            unpack2(c2[i][0], e[0], e[1]); unpack2(c2[i][1], e[2], e[3]);
            unpack2(c2[i][2], e[4], e[5]); unpack2(c2[i][3], e[6], e[7]);
            float4 p0, p1;
            p0.x = fexp2(e[0] - al[i]); p0.y = fexp2(e[1] - al[i]);
            p0.z = fexp2(e[2] - al[i]); p0.w = fexp2(e[3] - al[i]);
            p1.x = fexp2(e[4] - al[i]); p1.y = fexp2(e[5] - al[i]);
            p1.z = fexp2(e[6] - al[i]); p1.w = fexp2(e[7] - al[i]);
            *(float4*)&Ps[(ty * 8 + i) * PSS + tx * 8]     = p0;
            *(float4*)&Ps[(ty * 8 + i) * PSS + tx * 8 + 4] = p1;
        }
        __syncthreads();

#pragma unroll 4
        for (int nn = 0; nn < 128; nn++) {
            ulonglong2 pv = *(const ulonglong2*)&Ps[nn * PSS + mbase];
#pragma unroll
            for (int i = 0; i < 4; i++) {
                u64 v = *(const u64*)&Vd[(ciBase + i) * 128 + nn];
                acc2[i][0] = fma2(v, pv.x, acc2[i][0]);
                acc2[i][1] = fma2(v, pv.y, acc2[i][1]);
            }
        }
        __syncthreads();
        if (more) {
            stt_dup(Ad, pre, tid); stt_dup(Vd, preV, tid);
            __syncthreads();
        }
    }

    // ---- fused epilogue: final conv + BN + SiLU + residual ----
    float* Ys   = sm;                    // [32][132] floats
    float2* W4d = (float2*)(sm + 8192);  // [32][256] dup
    float* s4s  = sm + 24576;
    float* b4s  = sm + 24832;

#pragma unroll
    for (int i = 0; i < 4; i++)
#pragma unroll
        for (int j = 0; j < 2; j++)
            *(u64*)&Ys[(ciBase + i) * PSS + mbase + 2 * j] = acc2[i][j];
    for (int idx = tid; idx < C_ * CI; idx += 256) {
        int k = idx & 31, co = idx >> 5;
        float v = w4[co * CI + k];
        W4d[k * 256 + co] = make_float2(v, v);
    }
    s4s[tid] = s4[tid];
    b4s[tid] = b4[tid];
    __syncthreads();

    int mg = tid & 7, cog = tid >> 3;
    int co0 = cog * 8;
#pragma unroll
    for (int pass = 0; pass < 2; pass++) {
        int cp = co0 + pass * 4;
        u64 e2[4][8];
#pragma unroll
        for (int i = 0; i < 4; i++)
#pragma unroll
            for (int j = 0; j < 8; j++) e2[i][j] = 0ull;
#pragma unroll 4
        for (int k = 0; k < CI; k++) {
            u64 yv[8];
#pragma unroll
            for (int j = 0; j < 8; j++)
                yv[j] = *(const u64*)&Ys[k * PSS + 2 * (mg + 8 * j)];
#pragma unroll
            for (int i = 0; i < 4; i++) {
                u64 wv = *(const u64*)&W4d[k * 256 + cp + i];
#pragma unroll
                for (int j = 0; j < 8; j++) e2[i][j] = fma2(wv, yv[j], e2[i][j]);
            }
        }
#pragma unroll
        for (int i = 0; i < 4; i++) {
            float sc = s4s[cp + i], bi = b4s[cp + i];
            int rowoff = b * C_ * N_ + (cp + i) * N_ + m0;
#pragma unroll
            for (int j = 0; j < 8; j++) {
                float v0, v1;
                unpack2(e2[i][j], v0, v1);
                float y0 = fmaf(v0, sc, bi), y1 = fmaf(v1, sc, bi);
                float o0 = y0 * frcp(1.f + fexp2(-y0 * L2E));
                float o1 = y1 * frcp(1.f + fexp2(-y1 * L2E));
                int m = 2 * (mg + 8 * j);
                float2 xr = *(const float2*)&x[rowoff + m];
                float2 ov = make_float2(o0 + xr.x, o1 + xr.y);
                *(float2*)&out[rowoff + m] = ov;
            }
        }
    }
}

// ---------------------------------------------------------------------------
extern "C" void kernel_launch(void* const* d_in, const int* in_sizes, int n_in,
                              void* d_out, int out_size) {
    (void)in_sizes; (void)n_in; (void)out_size;
    const float* x  = (const float*)d_in[0];
    const float* w1 = (const float*)d_in[1];
    const float* s1 = (const float*)d_in[2];
    const float* b1 = (const float*)d_in[3];
    const float* w2 = (const float*)d_in[4];
    const float* s2 = (const float*)d_in[5];
    const float* b2 = (const float*)d_in[6];
    const float* w3 = (const float*)d_in[7];
    const float* s3 = (const float*)d_in[8];
    const float* b3 = (const float*)d_in[9];
    const float* w4 = (const float*)d_in[10];
    const float* s4 = (const float*)d_in[11];
    const float* b4 = (const float*)d_in[12];
    float* out = (float*)d_out;

    cudaFuncSetAttribute(k1_conv, cudaFuncAttributeMaxDynamicSharedMemorySize, 99072);
    cudaFuncSetAttribute(k2_stats, cudaFuncAttributeMaxDynamicSharedMemorySize, 49152);
    cudaFuncSetAttribute(k3_attn, cudaFuncAttributeMaxDynamicSharedMemorySize, 149504);

    k0_prep<<<96, 256>>>(w1, w2, w3);
    k1_conv<<<128, 256, 99072>>>(x, s1, b1, s2, b2, s3, b3);
    k2_stats<<<dim3(32, B_), 256, 49152>>>();
    k3_attn<<<dim3(32, B_), 256, 149504>>>(w4, s4, b4, x, out);
}

// round 6
// speedup vs baseline: 1.5375x; 1.3257x over previous
#include <cuda_runtime.h>

#define DEV_INLINE __device__ __forceinline__
typedef unsigned long long u64;

constexpr int B_ = 8;
constexpr int C_ = 256;
constexpr int CI = 32;
constexpr int N_ = 4096;
constexpr float L2E = 1.4426950408889634f;

__device__ __align__(128) float g_y1[B_ * CI * N_];
__device__ __align__(128) float g_y2[B_ * CI * N_];   // pre-scaled by log2(e)
__device__ __align__(128) float g_y3[B_ * CI * N_];
__device__ __align__(128) float g_alpha[B_ * N_];     // M*log2e + log2(Z)
__device__ __align__(128) float g_wAll[C_ * 96];

DEV_INLINE float fexp2(float v) { float y; asm("ex2.approx.ftz.f32 %0, %1;" : "=f"(y) : "f"(v)); return y; }
DEV_INLINE float flog2(float v) { float y; asm("lg2.approx.ftz.f32 %0, %1;" : "=f"(y) : "f"(v)); return y; }
DEV_INLINE float frcp(float v)  { float y; asm("rcp.approx.ftz.f32 %0, %1;" : "=f"(y) : "f"(v)); return y; }
DEV_INLINE u64 pack2(float lo, float hi) {
    u64 r; asm("mov.b64 %0, {%1,%2};" : "=l"(r) : "r"(__float_as_uint(lo)), "r"(__float_as_uint(hi)));
    return r;
}
DEV_INLINE void unpack2(u64 v, float& lo, float& hi) {
    unsigned a, b; asm("mov.b64 {%0,%1}, %2;" : "=r"(a), "=r"(b) : "l"(v));
    lo = __uint_as_float(a); hi = __uint_as_float(b);
}
DEV_INLINE u64 fma2(u64 a, u64 b, u64 c) {
    u64 d; asm("fma.rn.f32x2 %0, %1, %2, %3;" : "=l"(d) : "l"(a), "l"(b), "l"(c));
    return d;
}

// gmem [32][64] tile (row stride N_) -> 4 float4 regs (128 threads)
DEV_INLINE void ldt64(const float* __restrict__ src, int col0, float4 pre[4], int tid) {
#pragma unroll
    for (int s = 0; s < 4; s++) {
        int idx = tid + s * 128;
        pre[s] = *(const float4*)&src[(idx >> 4) * N_ + col0 + ((idx & 15) << 2)];
    }
}
DEV_INLINE void stt68(float* dst, const float4 pre[4], int tid) {
#pragma unroll
    for (int s = 0; s < 4; s++) {
        int idx = tid + s * 128;
        *(float4*)&dst[(idx >> 4) * 68 + ((idx & 15) << 2)] = pre[s];
    }
}

// GEMM1 core: rows = As ty*4+{0..3}; cols j0,1 -> m=tx*4+{0..3}, j2,3 -> m=32+tx*4+{0..3}
DEV_INLINE void gemm1(const float* As, const float* Bs, int ty, int tx, u64 c2[4][4]) {
#pragma unroll 4
    for (int k = 0; k < CI; k++) {
        float4 af = *(const float4*)&As[k * 68 + ty * 4];
        u64 a[4] = {pack2(af.x, af.x), pack2(af.y, af.y),
                    pack2(af.z, af.z), pack2(af.w, af.w)};
        ulonglong2 b0 = *(const ulonglong2*)&Bs[k * 68 + tx * 4];
        ulonglong2 b1 = *(const ulonglong2*)&Bs[k * 68 + 32 + tx * 4];
#pragma unroll
        for (int i = 0; i < 4; i++) {
            c2[i][0] = fma2(a[i], b0.x, c2[i][0]);
            c2[i][1] = fma2(a[i], b0.y, c2[i][1]);
            c2[i][2] = fma2(a[i], b1.x, c2[i][2]);
            c2[i][3] = fma2(a[i], b1.y, c2[i][3]);
        }
    }
}

__global__ void k0_prep(const float* __restrict__ w1, const float* __restrict__ w2,
                        const float* __restrict__ w3) {
    int i = blockIdx.x * 256 + threadIdx.x;
    if (i < C_ * 96) {
        int k = i / 96, j = i - k * 96;
        int br = j >> 5, co = j & 31;
        const float* w = br == 0 ? w1 : br == 1 ? w2 : w3;
        g_wAll[i] = w[co * C_ + k];
    }
}

// K1: three branch convs fused; grid 128, block 256, dyn smem 99072
__global__ void __launch_bounds__(256, 1) k1_conv(
    const float* __restrict__ x,
    const float* __restrict__ s1, const float* __restrict__ b1,
    const float* __restrict__ s2, const float* __restrict__ b2,
    const float* __restrict__ s3, const float* __restrict__ b3) {
    extern __shared__ float sm[];
    float* wAll = sm;
    float* sAll = sm + 24576;
    float* bAll = sAll + 96;
    int tid = threadIdx.x;
    const float4* wsrc = (const float4*)g_wAll;
#pragma unroll
    for (int s = 0; s < 24; s++) ((float4*)wAll)[tid + s * 256] = wsrc[tid + s * 256];
    if (tid < 96) {
        sAll[tid] = tid < 32 ? s1[tid] : tid < 64 ? s2[tid - 32] : s3[tid - 64];
        bAll[tid] = tid < 32 ? b1[tid] : tid < 64 ? b2[tid - 32] : b3[tid - 64];
    }
    __syncthreads();

    int gpos = blockIdx.x * 256 + tid;
    int b = gpos >> 12, m = gpos & (N_ - 1);
    const float* xp = x + b * C_ * N_ + m;
    u64 acc2[48];
#pragma unroll
    for (int i = 0; i < 48; i++) acc2[i] = 0ull;
#pragma unroll 2
    for (int k = 0; k < C_; k++) {
        float xv = __ldg(&xp[k * N_]);
        u64 xq = pack2(xv, xv);
        const ulonglong2* wk = (const ulonglong2*)&wAll[k * 96];
#pragma unroll
        for (int t = 0; t < 24; t++) {
            ulonglong2 wv = wk[t];
            acc2[2 * t]     = fma2(xq, wv.x, acc2[2 * t]);
            acc2[2 * t + 1] = fma2(xq, wv.y, acc2[2 * t + 1]);
        }
    }
    float* outs[3] = {g_y1, g_y2, g_y3};
#pragma unroll
    for (int br = 0; br < 3; br++) {
        float* op = outs[br] + b * CI * N_ + m;
        float mulf = (br == 1) ? L2E : 1.f;
#pragma unroll
        for (int p = 0; p < 16; p++) {
            int co = 2 * p;
            float v0, v1;
            unpack2(acc2[br * 16 + p], v0, v1);
            float y0 = fmaf(v0, sAll[br * 32 + co], bAll[br * 32 + co]);
            float y1 = fmaf(v1, sAll[br * 32 + co + 1], bAll[br * 32 + co + 1]);
            op[co * N_]       = y0 * frcp(1.f + fexp2(-y0 * L2E)) * mulf;
            op[(co + 1) * N_] = y1 * frcp(1.f + fexp2(-y1 * L2E)) * mulf;
        }
    }
}

// K2: softmax stats; grid (64,8), block 128
__global__ void __launch_bounds__(128, 6) k2_stats() {
    __shared__ float As[32 * 68], Bs[32 * 68];
    int b = blockIdx.y, n0 = blockIdx.x * 64;
    int tid = threadIdx.x, tx = tid & 7, ty = tid >> 3;
    const float* y2b = g_y2 + b * CI * N_;
    const float* y1b = g_y1 + b * CI * N_;

    float4 pa[4], pb[4];
    ldt64(y2b, n0, pa, tid); stt68(As, pa, tid);
    ldt64(y1b, 0, pb, tid);  stt68(Bs, pb, tid);
    __syncthreads();

    float runM[4], runL[4];
#pragma unroll
    for (int i = 0; i < 4; i++) { runM[i] = -1.0e30f; runL[i] = 0.f; }

    for (int t = 0; t < N_ / 64; t++) {
        bool more = t + 1 < N_ / 64;
        if (more) ldt64(y1b, (t + 1) * 64, pb, tid);
        u64 c2[4][4];
#pragma unroll
        for (int i = 0; i < 4; i++)
#pragma unroll
            for (int j = 0; j < 4; j++) c2[i][j] = 0ull;
        gemm1(As, Bs, ty, tx, c2);
#pragma unroll
        for (int i = 0; i < 4; i++) {
            float e[8];
            unpack2(c2[i][0], e[0], e[1]); unpack2(c2[i][1], e[2], e[3]);
            unpack2(c2[i][2], e[4], e[5]); unpack2(c2[i][3], e[6], e[7]);
            float mx = fmaxf(fmaxf(fmaxf(e[0], e[1]), fmaxf(e[2], e[3])),
                             fmaxf(fmaxf(e[4], e[5]), fmaxf(e[6], e[7])));
            float nM = fmaxf(runM[i], mx);
            float s = (fexp2(e[0] - nM) + fexp2(e[1] - nM)) + (fexp2(e[2] - nM) + fexp2(e[3] - nM))
                    + (fexp2(e[4] - nM) + fexp2(e[5] - nM)) + (fexp2(e[6] - nM) + fexp2(e[7] - nM));
            runL[i] = fmaf(runL[i], fexp2(runM[i] - nM), s);
            runM[i] = nM;
        }
        __syncthreads();
        if (more) stt68(Bs, pb, tid);
        __syncthreads();
    }
#pragma unroll
    for (int i = 0; i < 4; i++) {
        float M = runM[i], Z = runL[i];
#pragma unroll
        for (int off = 1; off < 8; off <<= 1) {
            float Mo = __shfl_xor_sync(0xffffffffu, M, off, 8);
            float Zo = __shfl_xor_sync(0xffffffffu, Z, off, 8);
            float nM = fmaxf(M, Mo);
            Z = fmaf(Z, fexp2(M - nM), Zo * fexp2(Mo - nM));
            M = nM;
        }
        if (tx == 0) g_alpha[b * N_ + n0 + ty * 4 + i] = M + flog2(Z);
    }
}

// K3: attention apply + fused final conv + SiLU + residual.
// grid (64,8), block 128, dyn smem 44032
__global__ void __launch_bounds__(128, 4) k3_attn(
    const float* __restrict__ w4, const float* __restrict__ s4,
    const float* __restrict__ b4, const float* __restrict__ x,
    float* __restrict__ out) {
    extern __shared__ float sm[];
    float* As = sm;            // [32][68] y2 n-tile
    float* Vs = sm + 2176;     // [32][68] y3 n-tile (natural layout)
    float* B1 = sm + 4352;     // [32][68] y1 m-tile
    float* Ps = sm + 6528;     // [64][68] P tile
    int b = blockIdx.y, m0 = blockIdx.x * 64;
    int tid = threadIdx.x, tx = tid & 7, ty = tid >> 3;
    int mg = tid & 15, cg = tid >> 4;
    const float* y1b = g_y1 + b * CI * N_;
    const float* y2b = g_y2 + b * CI * N_;
    const float* y3b = g_y3 + b * CI * N_;
    const float* alb = g_alpha + b * N_;

    float4 p1[4], p2[4], p3[4];
    ldt64(y1b, m0, p1, tid); stt68(B1, p1, tid);
    ldt64(y2b, 0, p2, tid);  stt68(As, p2, tid);
    ldt64(y3b, 0, p3, tid);  stt68(Vs, p3, tid);
    float4 alr = *(const float4*)&alb[ty * 4];
    __syncthreads();

    u64 acc[4][2];
#pragma unroll
    for (int i = 0; i < 4; i++) { acc[i][0] = 0ull; acc[i][1] = 0ull; }

    for (int t = 0; t < N_ / 64; t++) {
        bool more = t + 1 < N_ / 64;
        float4 aln = alr;
        if (more) {
            ldt64(y2b, (t + 1) * 64, p2, tid);
            ldt64(y3b, (t + 1) * 64, p3, tid);
            aln = *(const float4*)&alb[(t + 1) * 64 + ty * 4];
        }
        u64 c2[4][4];
#pragma unroll
        for (int i = 0; i < 4; i++)
#pragma unroll
            for (int j = 0; j < 4; j++) c2[i][j] = 0ull;
        gemm1(As, B1, ty, tx, c2);

        float al[4] = {alr.x, alr.y, alr.z, alr.w};
#pragma unroll
        for (int i = 0; i < 4; i++) {
            float e[8];
            unpack2(c2[i][0], e[0], e[1]); unpack2(c2[i][1], e[2], e[3]);
            unpack2(c2[i][2], e[4], e[5]); unpack2(c2[i][3], e[6], e[7]);
            float4 q0 = make_float4(fexp2(e[0] - al[i]), fexp2(e[1] - al[i]),
                                    fexp2(e[2] - al[i]), fexp2(e[3] - al[i]));
            float4 q1 = make_float4(fexp2(e[4] - al[i]), fexp2(e[5] - al[i]),
                                    fexp2(e[6] - al[i]), fexp2(e[7] - al[i]));
            *(float4*)&Ps[(ty * 4 + i) * 68 + tx * 4]      = q0;
            *(float4*)&Ps[(ty * 4 + i) * 68 + 32 + tx * 4] = q1;
        }
        __syncthreads();

        // GEMM2: thread = 4 ci (cg*4..) x 4 m (mg*4..); V scalar broadcast loads.
        const float* vrow0 = &Vs[(cg * 4 + 0) * 68];
        const float* vrow1 = &Vs[(cg * 4 + 1) * 68];
        const float* vrow2 = &Vs[(cg * 4 + 2) * 68];
        const float* vrow3 = &Vs[(cg * 4 + 3) * 68];
#pragma unroll 4
        for (int nn = 0; nn < 64; nn++) {
            ulonglong2 pv = *(const ulonglong2*)&Ps[nn * 68 + mg * 4];
            u64 v0 = pack2(vrow0[nn], vrow0[nn]);
            u64 v1 = pack2(vrow1[nn], vrow1[nn]);
            u64 v2 = pack2(vrow2[nn], vrow2[nn]);
            u64 v3 = pack2(vrow3[nn], vrow3[nn]);
            acc[0][0] = fma2(v0, pv.x, acc[0][0]); acc[0][1] = fma2(v0, pv.y, acc[0][1]);
            acc[1][0] = fma2(v1, pv.x, acc[1][0]); acc[1][1] = fma2(v1, pv.y, acc[1][1]);
            acc[2][0] = fma2(v2, pv.x, acc[2][0]); acc[2][1] = fma2(v2, pv.y, acc[2][1]);
            acc[3][0] = fma2(v3, pv.x, acc[3][0]); acc[3][1] = fma2(v3, pv.y, acc[3][1]);
        }
        __syncthreads();
        if (more) {
            stt68(As, p2, tid);
            stt68(Vs, p3, tid);
            alr = aln;
            __syncthreads();
        }
    }

    // epilogue: Ys[ci][m], W4t[k][co], then conv+SiLU+residual
    float* Ys  = sm;           // [32][68]
    float* W4t = sm + 2176;    // [32][260]
    float* s4s = sm + 10496;   // [256]
    float* b4s = sm + 10752;   // [256]
#pragma unroll
    for (int i = 0; i < 4; i++) {
        *(u64*)&Ys[(cg * 4 + i) * 68 + mg * 4]     = acc[i][0];
        *(u64*)&Ys[(cg * 4 + i) * 68 + mg * 4 + 2] = acc[i][1];
    }
    for (int idx = tid; idx < C_ * CI; idx += 128) {
        int co = idx >> 5, k = idx & 31;
        W4t[k * 260 + co] = w4[idx];
    }
    s4s[tid] = s4[tid]; s4s[tid + 128] = s4[tid + 128];
    b4s[tid] = b4[tid]; b4s[tid + 128] = b4[tid + 128];
    __syncthreads();

#pragma unroll
    for (int pass = 0; pass < 2; pass++) {
        int co0 = cg * 16 + pass * 128;
        u64 e2[16][2];
#pragma unroll
        for (int j = 0; j < 16; j++) { e2[j][0] = 0ull; e2[j][1] = 0ull; }
#pragma unroll 4
        for (int k = 0; k < CI; k++) {
            ulonglong2 ym = *(const ulonglong2*)&Ys[k * 68 + mg * 4];
#pragma unroll
            for (int q = 0; q < 4; q++) {
                float4 wq = *(const float4*)&W4t[k * 260 + co0 + q * 4];
                u64 w0 = pack2(wq.x, wq.x), w1 = pack2(wq.y, wq.y);
                u64 w2 = pack2(wq.z, wq.z), w3 = pack2(wq.w, wq.w);
                e2[q * 4 + 0][0] = fma2(w0, ym.x, e2[q * 4 + 0][0]);
                e2[q * 4 + 0][1] = fma2(w0, ym.y, e2[q * 4 + 0][1]);
                e2[q * 4 + 1][0] = fma2(w1, ym.x, e2[q * 4 + 1][0]);
                e2[q * 4 + 1][1] = fma2(w1, ym.y, e2[q * 4 + 1][1]);
                e2[q * 4 + 2][0] = fma2(w2, ym.x, e2[q * 4 + 2][0]);
                e2[q * 4 + 2][1] = fma2(w2, ym.y, e2[q * 4 + 2][1]);
                e2[q * 4 + 3][0] = fma2(w3, ym.x, e2[q * 4 + 3][0]);
                e2[q * 4 + 3][1] = fma2(w3, ym.y, e2[q * 4 + 3][1]);
            }
        }
#pragma unroll
        for (int j = 0; j < 16; j++) {
            int co = co0 + j;
            float sc = s4s[co], bi = b4s[co];
            float v0, v1, v2, v3;
            unpack2(e2[j][0], v0, v1); unpack2(e2[j][1], v2, v3);
            float y0 = fmaf(v0, sc, bi), y1 = fmaf(v1, sc, bi);
            float y2v = fmaf(v2, sc, bi), y3v = fmaf(v3, sc, bi);
            int off = b * C_ * N_ + co * N_ + m0 + mg * 4;
            float4 xr = *(const float4*)&x[off];
            float4 ov;
            ov.x = fmaf(y0,  frcp(1.f + fexp2(-y0 * L2E)),  xr.x);
            ov.y = fmaf(y1,  frcp(1.f + fexp2(-y1 * L2E)),  xr.y);
            ov.z = fmaf(y2v, frcp(1.f + fexp2(-y2v * L2E)), xr.z);
            ov.w = fmaf(y3v, frcp(1.f + fexp2(-y3v * L2E)), xr.w);
            *(float4*)&out[off] = ov;
        }
    }
}

extern "C" void kernel_launch(void* const* d_in, const int* in_sizes, int n_in,
                              void* d_out, int out_size) {
    (void)in_sizes; (void)n_in; (void)out_size;
    const float* x  = (const float*)d_in[0];
    const float* w1 = (const float*)d_in[1];
    const float* s1 = (const float*)d_in[2];
    const float* b1 = (const float*)d_in[3];
    const float* w2 = (const float*)d_in[4];
    const float* s2 = (const float*)d_in[5];
    const float* b2 = (const float*)d_in[6];
    const float* w3 = (const float*)d_in[7];
    const float* s3 = (const float*)d_in[8];
    const float* b3 = (const float*)d_in[9];
    const float* w4 = (const float*)d_in[10];
    const float* s4 = (const float*)d_in[11];
    const float* b4 = (const float*)d_in[12];
    float* out = (float*)d_out;

    cudaFuncSetAttribute(k1_conv, cudaFuncAttributeMaxDynamicSharedMemorySize, 99072);
    cudaFuncSetAttribute(k3_attn, cudaFuncAttributeMaxDynamicSharedMemorySize, 44032);

    k0_prep<<<96, 256>>>(w1, w2, w3);
    k1_conv<<<128, 256, 99072>>>(x, s1, b1, s2, b2, s3, b3);
    k2_stats<<<dim3(64, B_), 128>>>();
    k3_attn<<<dim3(64, B_), 128, 44032>>>(w4, s4, b4, x, out);
}

// round 7
// speedup vs baseline: 1.6820x; 1.0940x over previous
#include <cuda_runtime.h>

#define DEV_INLINE __device__ __forceinline__
typedef unsigned long long u64;

constexpr int B_ = 8;
constexpr int C_ = 256;
constexpr int CI = 32;
constexpr int N_ = 4096;
constexpr int NS = 2;                   // n/m split factor
constexpr float L2E = 1.4426950408889634f;

__device__ __align__(128) float g_y1[B_ * CI * N_];
__device__ __align__(128) float g_y2[B_ * CI * N_];   // pre-scaled by log2(e)
__device__ __align__(128) float g_y3[B_ * CI * N_];
__device__ __align__(128) float g_alpha[B_ * N_];     // M*log2e + log2(Z)
__device__ __align__(128) float g_wAll[C_ * 96];
__device__ __align__(128) float g_part[NS * B_ * CI * N_];   // k3 partials
__device__ __align__(128) float2 g_mz[NS * B_ * N_];         // k2 partial (M,Z)

DEV_INLINE float fexp2(float v) { float y; asm("ex2.approx.ftz.f32 %0, %1;" : "=f"(y) : "f"(v)); return y; }
DEV_INLINE float flog2(float v) { float y; asm("lg2.approx.ftz.f32 %0, %1;" : "=f"(y) : "f"(v)); return y; }
DEV_INLINE float frcp(float v)  { float y; asm("rcp.approx.ftz.f32 %0, %1;" : "=f"(y) : "f"(v)); return y; }
DEV_INLINE u64 pack2(float lo, float hi) {
    u64 r; asm("mov.b64 %0, {%1,%2};" : "=l"(r) : "r"(__float_as_uint(lo)), "r"(__float_as_uint(hi)));
    return r;
}
DEV_INLINE void unpack2(u64 v, float& lo, float& hi) {
    unsigned a, b; asm("mov.b64 {%0,%1}, %2;" : "=r"(a), "=r"(b) : "l"(v));
    lo = __uint_as_float(a); hi = __uint_as_float(b);
}
DEV_INLINE u64 fma2(u64 a, u64 b, u64 c) {
    u64 d; asm("fma.rn.f32x2 %0, %1, %2, %3;" : "=l"(d) : "l"(a), "l"(b), "l"(c));
    return d;
}

// gmem [32][64] tile (row stride N_) -> 4 float4 regs (128 threads)
DEV_INLINE void ldt64(const float* __restrict__ src, int col0, float4 pre[4], int tid) {
#pragma unroll
    for (int s = 0; s < 4; s++) {
        int idx = tid + s * 128;
        pre[s] = *(const float4*)&src[(idx >> 4) * N_ + col0 + ((idx & 15) << 2)];
    }
}
DEV_INLINE void stt68(float* dst, const float4 pre[4], int tid) {
#pragma unroll
    for (int s = 0; s < 4; s++) {
        int idx = tid + s * 128;
        *(float4*)&dst[(idx >> 4) * 68 + ((idx & 15) << 2)] = pre[s];
    }
}

// GEMM1 core: rows = As ty*4+{0..3}; cols j0,1 -> m=tx*4+{0..3}, j2,3 -> m=32+tx*4+{0..3}
DEV_INLINE void gemm1(const float* As, const float* Bs, int ty, int tx, u64 c2[4][4]) {
#pragma unroll 4
    for (int k = 0; k < CI; k++) {
        float4 af = *(const float4*)&As[k * 68 + ty * 4];
        u64 a[4] = {pack2(af.x, af.x), pack2(af.y, af.y),
                    pack2(af.z, af.z), pack2(af.w, af.w)};
        ulonglong2 b0 = *(const ulonglong2*)&Bs[k * 68 + tx * 4];
        ulonglong2 b1 = *(const ulonglong2*)&Bs[k * 68 + 32 + tx * 4];
#pragma unroll
        for (int i = 0; i < 4; i++) {
            c2[i][0] = fma2(a[i], b0.x, c2[i][0]);
            c2[i][1] = fma2(a[i], b0.y, c2[i][1]);
            c2[i][2] = fma2(a[i], b1.x, c2[i][2]);
            c2[i][3] = fma2(a[i], b1.y, c2[i][3]);
        }
    }
}

__global__ void k0_prep(const float* __restrict__ w1, const float* __restrict__ w2,
                        const float* __restrict__ w3) {
    int i = blockIdx.x * 256 + threadIdx.x;
    if (i < C_ * 96) {
        int k = i / 96, j = i - k * 96;
        int br = j >> 5, co = j & 31;
        const float* w = br == 0 ? w1 : br == 1 ? w2 : w3;
        g_wAll[i] = w[co * C_ + k];
    }
}

// K1: three branch convs fused; grid 128, block 256, dyn smem 99072
__global__ void __launch_bounds__(256, 1) k1_conv(
    const float* __restrict__ x,
    const float* __restrict__ s1, const float* __restrict__ b1,
    const float* __restrict__ s2, const float* __restrict__ b2,
    const float* __restrict__ s3, const float* __restrict__ b3) {
    extern __shared__ float sm[];
    float* wAll = sm;
    float* sAll = sm + 24576;
    float* bAll = sAll + 96;
    int tid = threadIdx.x;
    const float4* wsrc = (const float4*)g_wAll;
#pragma unroll
    for (int s = 0; s < 24; s++) ((float4*)wAll)[tid + s * 256] = wsrc[tid + s * 256];
    if (tid < 96) {
        sAll[tid] = tid < 32 ? s1[tid] : tid < 64 ? s2[tid - 32] : s3[tid - 64];
        bAll[tid] = tid < 32 ? b1[tid] : tid < 64 ? b2[tid - 32] : b3[tid - 64];
    }
    __syncthreads();

    int gpos = blockIdx.x * 256 + tid;
    int b = gpos >> 12, m = gpos & (N_ - 1);
    const float* xp = x + b * C_ * N_ + m;
    u64 acc2[48];
#pragma unroll
    for (int i = 0; i < 48; i++) acc2[i] = 0ull;
#pragma unroll 2
    for (int k = 0; k < C_; k++) {
        float xv = __ldg(&xp[k * N_]);
        u64 xq = pack2(xv, xv);
        const ulonglong2* wk = (const ulonglong2*)&wAll[k * 96];
#pragma unroll
        for (int t = 0; t < 24; t++) {
            ulonglong2 wv = wk[t];
            acc2[2 * t]     = fma2(xq, wv.x, acc2[2 * t]);
            acc2[2 * t + 1] = fma2(xq, wv.y, acc2[2 * t + 1]);
        }
    }
    float* outs[3] = {g_y1, g_y2, g_y3};
#pragma unroll
    for (int br = 0; br < 3; br++) {
        float* op = outs[br] + b * CI * N_ + m;
        float mulf = (br == 1) ? L2E : 1.f;
#pragma unroll
        for (int p = 0; p < 16; p++) {
            int co = 2 * p;
            float v0, v1;
            unpack2(acc2[br * 16 + p], v0, v1);
            float y0 = fmaf(v0, sAll[br * 32 + co], bAll[br * 32 + co]);
            float y1 = fmaf(v1, sAll[br * 32 + co + 1], bAll[br * 32 + co + 1]);
            op[co * N_]       = y0 * frcp(1.f + fexp2(-y0 * L2E)) * mulf;
            op[(co + 1) * N_] = y1 * frcp(1.f + fexp2(-y1 * L2E)) * mulf;
        }
    }
}

// K2: partial softmax stats over an m-half; grid (64,8,NS), block 128
__global__ void __launch_bounds__(128, 6) k2_stats() {
    __shared__ float As[32 * 68], Bs[32 * 68];
    int b = blockIdx.y, n0 = blockIdx.x * 64, hz = blockIdx.z;
    int t0 = hz * (N_ / 64 / NS);
    int tid = threadIdx.x, tx = tid & 7, ty = tid >> 3;
    const float* y2b = g_y2 + b * CI * N_;
    const float* y1b = g_y1 + b * CI * N_;

    float4 pa[4], pb[4];
    ldt64(y2b, n0, pa, tid); stt68(As, pa, tid);
    ldt64(y1b, t0 * 64, pb, tid); stt68(Bs, pb, tid);
    __syncthreads();

    float runM[4], runL[4];
#pragma unroll
    for (int i = 0; i < 4; i++) { runM[i] = -1.0e30f; runL[i] = 0.f; }

    for (int t = t0; t < t0 + N_ / 64 / NS; t++) {
        bool more = t + 1 < t0 + N_ / 64 / NS;
        if (more) ldt64(y1b, (t + 1) * 64, pb, tid);
        u64 c2[4][4];
#pragma unroll
        for (int i = 0; i < 4; i++)
#pragma unroll
            for (int j = 0; j < 4; j++) c2[i][j] = 0ull;
        gemm1(As, Bs, ty, tx, c2);
#pragma unroll
        for (int i = 0; i < 4; i++) {
            float e[8];
            unpack2(c2[i][0], e[0], e[1]); unpack2(c2[i][1], e[2], e[3]);
            unpack2(c2[i][2], e[4], e[5]); unpack2(c2[i][3], e[6], e[7]);
            float mx = fmaxf(fmaxf(fmaxf(e[0], e[1]), fmaxf(e[2], e[3])),
                             fmaxf(fmaxf(e[4], e[5]), fmaxf(e[6], e[7])));
            float nM = fmaxf(runM[i], mx);
            float s = (fexp2(e[0] - nM) + fexp2(e[1] - nM)) + (fexp2(e[2] - nM) + fexp2(e[3] - nM))
                    + (fexp2(e[4] - nM) + fexp2(e[5] - nM)) + (fexp2(e[6] - nM) + fexp2(e[7] - nM));
            runL[i] = fmaf(runL[i], fexp2(runM[i] - nM), s);
            runM[i] = nM;
        }
        __syncthreads();
        if (more) stt68(Bs, pb, tid);
        __syncthreads();
    }
#pragma unroll
    for (int i = 0; i < 4; i++) {
        float M = runM[i], Z = runL[i];
#pragma unroll
        for (int off = 1; off < 8; off <<= 1) {
            float Mo = __shfl_xor_sync(0xffffffffu, M, off, 8);
            float Zo = __shfl_xor_sync(0xffffffffu, Z, off, 8);
            float nM = fmaxf(M, Mo);
            Z = fmaf(Z, fexp2(M - nM), Zo * fexp2(Mo - nM));
            M = nM;
        }
        if (tx == 0) g_mz[(hz * B_ + b) * N_ + n0 + ty * 4 + i] = make_float2(M, Z);
    }
}

// K2b: merge NS partial (M,Z) -> alpha
__global__ void k2b_merge() {
    int i = blockIdx.x * 256 + threadIdx.x;
    if (i < B_ * N_) {
        float2 a = g_mz[i], c = g_mz[B_ * N_ + i];
        float M = fmaxf(a.x, c.x);
        float Z = a.y * fexp2(a.x - M) + c.y * fexp2(c.x - M);
        g_alpha[i] = M + flog2(Z);
    }
}

// K3: attention apply over an n-half, writes partial y_last.
// grid (64,8,NS), block 128, dyn smem 43520
__global__ void __launch_bounds__(128, 4) k3_attn(const float* __restrict__ dummy) {
    extern __shared__ float sm[];
    float* As = sm;            // [32][68] y2 n-tile
    float* Vs = sm + 2176;     // [32][68] y3 n-tile
    float* B1 = sm + 4352;     // [32][68] y1 m-tile
    float* Ps = sm + 6528;     // [64][68] P tile
    int b = blockIdx.y, m0 = blockIdx.x * 64, hz = blockIdx.z;
    int t0 = hz * (N_ / 64 / NS);
    int tid = threadIdx.x, tx = tid & 7, ty = tid >> 3;
    int mg = tid & 15, cg = tid >> 4;
    const float* y1b = g_y1 + b * CI * N_;
    const float* y2b = g_y2 + b * CI * N_;
    const float* y3b = g_y3 + b * CI * N_;
    const float* alb = g_alpha + b * N_;

    float4 p1[4], p2[4], p3[4];
    ldt64(y1b, m0, p1, tid); stt68(B1, p1, tid);
    ldt64(y2b, t0 * 64, p2, tid); stt68(As, p2, tid);
    ldt64(y3b, t0 * 64, p3, tid); stt68(Vs, p3, tid);
    float4 alr = *(const float4*)&alb[t0 * 64 + ty * 4];
    __syncthreads();

    u64 acc[4][2];
#pragma unroll
    for (int i = 0; i < 4; i++) { acc[i][0] = 0ull; acc[i][1] = 0ull; }

    for (int t = t0; t < t0 + N_ / 64 / NS; t++) {
        bool more = t + 1 < t0 + N_ / 64 / NS;
        float4 aln = alr;
        if (more) {
            ldt64(y2b, (t + 1) * 64, p2, tid);
            ldt64(y3b, (t + 1) * 64, p3, tid);
            aln = *(const float4*)&alb[(t + 1) * 64 + ty * 4];
        }
        u64 c2[4][4];
#pragma unroll
        for (int i = 0; i < 4; i++)
#pragma unroll
            for (int j = 0; j < 4; j++) c2[i][j] = 0ull;
        gemm1(As, B1, ty, tx, c2);

        float al[4] = {alr.x, alr.y, alr.z, alr.w};
#pragma unroll
        for (int i = 0; i < 4; i++) {
            float e[8];
            unpack2(c2[i][0], e[0], e[1]); unpack2(c2[i][1], e[2], e[3]);
            unpack2(c2[i][2], e[4], e[5]); unpack2(c2[i][3], e[6], e[7]);
            float4 q0 = make_float4(fexp2(e[0] - al[i]), fexp2(e[1] - al[i]),
                                    fexp2(e[2] - al[i]), fexp2(e[3] - al[i]));
            float4 q1 = make_float4(fexp2(e[4] - al[i]), fexp2(e[5] - al[i]),
                                    fexp2(e[6] - al[i]), fexp2(e[7] - al[i]));
            *(float4*)&Ps[(ty * 4 + i) * 68 + tx * 4]      = q0;
            *(float4*)&Ps[(ty * 4 + i) * 68 + 32 + tx * 4] = q1;
        }
        __syncthreads();   // bar1: Ps ready; all GEMM1 reads done

        // GEMM2: thread = 4ci x 4m; V loaded as float4 over nn (4 nn per chunk).
        const float* vr0 = &Vs[(cg * 4 + 0) * 68];
        const float* vr1 = &Vs[(cg * 4 + 1) * 68];
        const float* vr2 = &Vs[(cg * 4 + 2) * 68];
        const float* vr3 = &Vs[(cg * 4 + 3) * 68];
#pragma unroll 2
        for (int nc = 0; nc < 16; nc++) {
            float4 v0 = *(const float4*)&vr0[nc * 4];
            float4 v1 = *(const float4*)&vr1[nc * 4];
            float4 v2 = *(const float4*)&vr2[nc * 4];
            float4 v3 = *(const float4*)&vr3[nc * 4];
            float a0[4] = {v0.x, v0.y, v0.z, v0.w};
            float a1[4] = {v1.x, v1.y, v1.z, v1.w};
            float a2[4] = {v2.x, v2.y, v2.z, v2.w};
            float a3[4] = {v3.x, v3.y, v3.z, v3.w};
#pragma unroll
            for (int j = 0; j < 4; j++) {
                ulonglong2 pv = *(const ulonglong2*)&Ps[(nc * 4 + j) * 68 + mg * 4];
                u64 w0 = pack2(a0[j], a0[j]), w1 = pack2(a1[j], a1[j]);
                u64 w2 = pack2(a2[j], a2[j]), w3 = pack2(a3[j], a3[j]);
                acc[0][0] = fma2(w0, pv.x, acc[0][0]); acc[0][1] = fma2(w0, pv.y, acc[0][1]);
                acc[1][0] = fma2(w1, pv.x, acc[1][0]); acc[1][1] = fma2(w1, pv.y, acc[1][1]);
                acc[2][0] = fma2(w2, pv.x, acc[2][0]); acc[2][1] = fma2(w2, pv.y, acc[2][1]);
                acc[3][0] = fma2(w3, pv.x, acc[3][0]); acc[3][1] = fma2(w3, pv.y, acc[3][1]);
            }
        }
        if (more) stt68(As, p2, tid);   // safe: all GEMM1 reads done at bar1
        __syncthreads();                // bar2: all GEMM2 reads of Vs/Ps done
        if (more) { stt68(Vs, p3, tid); alr = aln; }
    }

    // write partial y_last tile
    float* pp = g_part + (hz * B_ + b) * CI * N_;
#pragma unroll
    for (int i = 0; i < 4; i++) {
        float4 o;
        unpack2(acc[i][0], o.x, o.y);
        unpack2(acc[i][1], o.z, o.w);
        *(float4*)&pp[(cg * 4 + i) * N_ + m0 + mg * 4] = o;
    }
    (void)dummy;
}

// K4: reduce NS partials + final conv + BN + SiLU + residual. grid (64,8), block 128
__global__ void __launch_bounds__(128) k4_epi(
    const float* __restrict__ w4, const float* __restrict__ s4,
    const float* __restrict__ b4, const float* __restrict__ x,
    float* __restrict__ out) {
    __shared__ float Ys[32 * 68];
    __shared__ float W4t[32 * 260];
    __shared__ float s4s[256], b4s[256];
    int b = blockIdx.y, m0 = blockIdx.x * 64;
    int tid = threadIdx.x;
    int mg = tid & 15, cg = tid >> 4;

    const float* q0 = g_part + b * CI * N_;
    const float* q1 = g_part + (B_ + b) * CI * N_;
#pragma unroll
    for (int s = 0; s < 4; s++) {
        int idx = tid + s * 128;               // float4 index within [32][64]
        int ci = idx >> 4, off = (idx & 15) << 2;
        float4 u = *(const float4*)&q0[ci * N_ + m0 + off];
        float4 v = *(const float4*)&q1[ci * N_ + m0 + off];
        u.x += v.x; u.y += v.y; u.z += v.z; u.w += v.w;
        *(float4*)&Ys[ci * 68 + off] = u;
    }
    for (int idx = tid; idx < C_ * CI; idx += 128) {
        int co = idx >> 5, k = idx & 31;
        W4t[k * 260 + co] = w4[idx];
    }
    s4s[tid] = s4[tid]; s4s[tid + 128] = s4[tid + 128];
    b4s[tid] = b4[tid]; b4s[tid + 128] = b4[tid + 128];
    __syncthreads();

#pragma unroll
    for (int pass = 0; pass < 2; pass++) {
        int co0 = cg * 16 + pass * 128;
        u64 e2[16][2];
#pragma unroll
        for (int j = 0; j < 16; j++) { e2[j][0] = 0ull; e2[j][1] = 0ull; }
#pragma unroll 4
        for (int k = 0; k < CI; k++) {
            ulonglong2 ym = *(const ulonglong2*)&Ys[k * 68 + mg * 4];
#pragma unroll
            for (int q = 0; q < 4; q++) {
                float4 wq = *(const float4*)&W4t[k * 260 + co0 + q * 4];
                u64 w0 = pack2(wq.x, wq.x), w1 = pack2(wq.y, wq.y);
                u64 w2 = pack2(wq.z, wq.z), w3 = pack2(wq.w, wq.w);
                e2[q * 4 + 0][0] = fma2(w0, ym.x, e2[q * 4 + 0][0]);
                e2[q * 4 + 0][1] = fma2(w0, ym.y, e2[q * 4 + 0][1]);
                e2[q * 4 + 1][0] = fma2(w1, ym.x, e2[q * 4 + 1][0]);
                e2[q * 4 + 1][1] = fma2(w1, ym.y, e2[q * 4 + 1][1]);
                e2[q * 4 + 2][0] = fma2(w2, ym.x, e2[q * 4 + 2][0]);
                e2[q * 4 + 2][1] = fma2(w2, ym.y, e2[q * 4 + 2][1]);
                e2[q * 4 + 3][0] = fma2(w3, ym.x, e2[q * 4 + 3][0]);
                e2[q * 4 + 3][1] = fma2(w3, ym.y, e2[q * 4 + 3][1]);
            }
        }
#pragma unroll
        for (int j = 0; j < 16; j++) {
            int co = co0 + j;
            float sc = s4s[co], bi = b4s[co];
            float v0, v1, v2, v3;
            unpack2(e2[j][0], v0, v1); unpack2(e2[j][1], v2, v3);
            float y0 = fmaf(v0, sc, bi), y1 = fmaf(v1, sc, bi);
            float y2v = fmaf(v2, sc, bi), y3v = fmaf(v3, sc, bi);
            int off = b * C_ * N_ + co * N_ + m0 + mg * 4;
            float4 xr = *(const float4*)&x[off];
            float4 ov;
            ov.x = fmaf(y0,  frcp(1.f + fexp2(-y0 * L2E)),  xr.x);
            ov.y = fmaf(y1,  frcp(1.f + fexp2(-y1 * L2E)),  xr.y);
            ov.z = fmaf(y2v, frcp(1.f + fexp2(-y2v * L2E)), xr.z);
            ov.w = fmaf(y3v, frcp(1.f + fexp2(-y3v * L2E)), xr.w);
            *(float4*)&out[off] = ov;
        }
    }
}

extern "C" void kernel_launch(void* const* d_in, const int* in_sizes, int n_in,
                              void* d_out, int out_size) {
    (void)in_sizes; (void)n_in; (void)out_size;
    const float* x  = (const float*)d_in[0];
    const float* w1 = (const float*)d_in[1];
    const float* s1 = (const float*)d_in[2];
    const float* b1 = (const float*)d_in[3];
    const float* w2 = (const float*)d_in[4];
    const float* s2 = (const float*)d_in[5];
    const float* b2 = (const float*)d_in[6];
    const float* w3 = (const float*)d_in[7];
    const float* s3 = (const float*)d_in[8];
    const float* b3 = (const float*)d_in[9];
    const float* w4 = (const float*)d_in[10];
    const float* s4 = (const float*)d_in[11];
    const float* b4 = (const float*)d_in[12];
    float* out = (float*)d_out;

    cudaFuncSetAttribute(k1_conv, cudaFuncAttributeMaxDynamicSharedMemorySize, 99072);
    cudaFuncSetAttribute(k3_attn, cudaFuncAttributeMaxDynamicSharedMemorySize, 43520);

    k0_prep<<<96, 256>>>(w1, w2, w3);
    k1_conv<<<128, 256, 99072>>>(x, s1, b1, s2, b2, s3, b3);
    k2_stats<<<dim3(64, B_, NS), 128>>>();
    k2b_merge<<<(B_ * N_ + 255) / 256, 256>>>();
    k3_attn<<<dim3(64, B_, NS), 128, 43520>>>(x);
    k4_epi<<<dim3(64, B_), 128>>>(w4, s4, b4, x, out);
}

// round 8
// speedup vs baseline: 1.7011x; 1.0114x over previous
#include <cuda_runtime.h>

#define DEV_INLINE __device__ __forceinline__
typedef unsigned long long u64;

constexpr int B_ = 8;
constexpr int C_ = 256;
constexpr int CI = 32;
constexpr int N_ = 4096;
constexpr int NS = 2;                   // n/m split factor
constexpr float L2E = 1.4426950408889634f;

__device__ __align__(128) float g_y1[B_ * CI * N_];
__device__ __align__(128) float g_y2[B_ * CI * N_];   // pre-scaled by log2(e)
__device__ __align__(128) float g_y3[B_ * CI * N_];
__device__ __align__(128) float g_alpha[B_ * N_];     // M*log2e + log2(Z)
__device__ __align__(128) float g_wAll[C_ * 96];
__device__ __align__(128) float g_part[NS * B_ * CI * N_];   // k3 partials
__device__ __align__(128) float2 g_mz[NS * B_ * N_];         // k2 partial (M,Z)

DEV_INLINE float fexp2(float v) { float y; asm("ex2.approx.ftz.f32 %0, %1;" : "=f"(y) : "f"(v)); return y; }
DEV_INLINE float flog2(float v) { float y; asm("lg2.approx.ftz.f32 %0, %1;" : "=f"(y) : "f"(v)); return y; }
DEV_INLINE float frcp(float v)  { float y; asm("rcp.approx.ftz.f32 %0, %1;" : "=f"(y) : "f"(v)); return y; }
DEV_INLINE u64 pack2(float lo, float hi) {
    u64 r; asm("mov.b64 %0, {%1,%2};" : "=l"(r) : "r"(__float_as_uint(lo)), "r"(__float_as_uint(hi)));
    return r;
}
DEV_INLINE void unpack2(u64 v, float& lo, float& hi) {
    unsigned a, b; asm("mov.b64 {%0,%1}, %2;" : "=r"(a), "=r"(b) : "l"(v));
    lo = __uint_as_float(a); hi = __uint_as_float(b);
}
DEV_INLINE u64 fma2(u64 a, u64 b, u64 c) {
    u64 d; asm("fma.rn.f32x2 %0, %1, %2, %3;" : "=l"(d) : "l"(a), "l"(b), "l"(c));
    return d;
}

// gmem [32][64] tile (row stride N_) -> 4 float4 regs (128 threads)
DEV_INLINE void ldt64(const float* __restrict__ src, int col0, float4 pre[4], int tid) {
#pragma unroll
    for (int s = 0; s < 4; s++) {
        int idx = tid + s * 128;
        pre[s] = *(const float4*)&src[(idx >> 4) * N_ + col0 + ((idx & 15) << 2)];
    }
}
DEV_INLINE void stt68(float* dst, const float4 pre[4], int tid) {
#pragma unroll
    for (int s = 0; s < 4; s++) {
        int idx = tid + s * 128;
        *(float4*)&dst[(idx >> 4) * 68 + ((idx & 15) << 2)] = pre[s];
    }
}

// GEMM1 core: rows = As ty*4+{0..3}; cols j0,1 -> m=tx*4+{0..3}, j2,3 -> m=32+tx*4+{0..3}
DEV_INLINE void gemm1(const float* As, const float* Bs, int ty, int tx, u64 c2[4][4]) {
#pragma unroll 4
    for (int k = 0; k < CI; k++) {
        float4 af = *(const float4*)&As[k * 68 + ty * 4];
        u64 a[4] = {pack2(af.x, af.x), pack2(af.y, af.y),
                    pack2(af.z, af.z), pack2(af.w, af.w)};
        ulonglong2 b0 = *(const ulonglong2*)&Bs[k * 68 + tx * 4];
        ulonglong2 b1 = *(const ulonglong2*)&Bs[k * 68 + 32 + tx * 4];
#pragma unroll
        for (int i = 0; i < 4; i++) {
            c2[i][0] = fma2(a[i], b0.x, c2[i][0]);
            c2[i][1] = fma2(a[i], b0.y, c2[i][1]);
            c2[i][2] = fma2(a[i], b1.x, c2[i][2]);
            c2[i][3] = fma2(a[i], b1.y, c2[i][3]);
        }
    }
}

__global__ void k0_prep(const float* __restrict__ w1, const float* __restrict__ w2,
                        const float* __restrict__ w3) {
    int i = blockIdx.x * 256 + threadIdx.x;
    if (i < C_ * 96) {
        int k = i / 96, j = i - k * 96;
        int br = j >> 5, co = j & 31;
        const float* w = br == 0 ? w1 : br == 1 ? w2 : w3;
        g_wAll[i] = w[co * C_ + k];
    }
}

// K1: three branch convs fused; grid 128, block 256, dyn smem 99072
__global__ void __launch_bounds__(256, 1) k1_conv(
    const float* __restrict__ x,
    const float* __restrict__ s1, const float* __restrict__ b1,
    const float* __restrict__ s2, const float* __restrict__ b2,
    const float* __restrict__ s3, const float* __restrict__ b3) {
    extern __shared__ float sm[];
    float* wAll = sm;
    float* sAll = sm + 24576;
    float* bAll = sAll + 96;
    int tid = threadIdx.x;
    const float4* wsrc = (const float4*)g_wAll;
#pragma unroll
    for (int s = 0; s < 24; s++) ((float4*)wAll)[tid + s * 256] = wsrc[tid + s * 256];
    if (tid < 96) {
        sAll[tid] = tid < 32 ? s1[tid] : tid < 64 ? s2[tid - 32] : s3[tid - 64];
        bAll[tid] = tid < 32 ? b1[tid] : tid < 64 ? b2[tid - 32] : b3[tid - 64];
    }
    __syncthreads();

    int gpos = blockIdx.x * 256 + tid;
    int b = gpos >> 12, m = gpos & (N_ - 1);
    const float* xp = x + b * C_ * N_ + m;
    u64 acc2[48];
#pragma unroll
    for (int i = 0; i < 48; i++) acc2[i] = 0ull;
#pragma unroll 2
    for (int k = 0; k < C_; k++) {
        float xv = __ldg(&xp[k * N_]);
        u64 xq = pack2(xv, xv);
        const ulonglong2* wk = (const ulonglong2*)&wAll[k * 96];
#pragma unroll
        for (int t = 0; t < 24; t++) {
            ulonglong2 wv = wk[t];
            acc2[2 * t]     = fma2(xq, wv.x, acc2[2 * t]);
            acc2[2 * t + 1] = fma2(xq, wv.y, acc2[2 * t + 1]);
        }
    }
    float* outs[3] = {g_y1, g_y2, g_y3};
#pragma unroll
    for (int br = 0; br < 3; br++) {
        float* op = outs[br] + b * CI * N_ + m;
        float mulf = (br == 1) ? L2E : 1.f;
#pragma unroll
        for (int p = 0; p < 16; p++) {
            int co = 2 * p;
            float v0, v1;
            unpack2(acc2[br * 16 + p], v0, v1);
            float y0 = fmaf(v0, sAll[br * 32 + co], bAll[br * 32 + co]);
            float y1 = fmaf(v1, sAll[br * 32 + co + 1], bAll[br * 32 + co + 1]);
            op[co * N_]       = y0 * frcp(1.f + fexp2(-y0 * L2E)) * mulf;
            op[(co + 1) * N_] = y1 * frcp(1.f + fexp2(-y1 * L2E)) * mulf;
        }
    }
}

// K2: partial softmax stats over an m-half; grid (64,8,NS), block 128
__global__ void __launch_bounds__(128, 6) k2_stats() {
    __shared__ float As[32 * 68], Bs[32 * 68];
    int b = blockIdx.y, n0 = blockIdx.x * 64, hz = blockIdx.z;
    int t0 = hz * (N_ / 64 / NS);
    int tid = threadIdx.x, tx = tid & 7, ty = tid >> 3;
    const float* y2b = g_y2 + b * CI * N_;
    const float* y1b = g_y1 + b * CI * N_;

    float4 pa[4], pb[4];
    ldt64(y2b, n0, pa, tid); stt68(As, pa, tid);
    ldt64(y1b, t0 * 64, pb, tid); stt68(Bs, pb, tid);
    __syncthreads();

    float runM[4], runL[4];
#pragma unroll
    for (int i = 0; i < 4; i++) { runM[i] = -1.0e30f; runL[i] = 0.f; }

    for (int t = t0; t < t0 + N_ / 64 / NS; t++) {
        bool more = t + 1 < t0 + N_ / 64 / NS;
        if (more) ldt64(y1b, (t + 1) * 64, pb, tid);
        u64 c2[4][4];
#pragma unroll
        for (int i = 0; i < 4; i++)
#pragma unroll
            for (int j = 0; j < 4; j++) c2[i][j] = 0ull;
        gemm1(As, Bs, ty, tx, c2);
#pragma unroll
        for (int i = 0; i < 4; i++) {
            float e[8];
            unpack2(c2[i][0], e[0], e[1]); unpack2(c2[i][1], e[2], e[3]);
            unpack2(c2[i][2], e[4], e[5]); unpack2(c2[i][3], e[6], e[7]);
            float mx = fmaxf(fmaxf(fmaxf(e[0], e[1]), fmaxf(e[2], e[3])),
                             fmaxf(fmaxf(e[4], e[5]), fmaxf(e[6], e[7])));
            float nM = fmaxf(runM[i], mx);
            float s = (fexp2(e[0] - nM) + fexp2(e[1] - nM)) + (fexp2(e[2] - nM) + fexp2(e[3] - nM))
                    + (fexp2(e[4] - nM) + fexp2(e[5] - nM)) + (fexp2(e[6] - nM) + fexp2(e[7] - nM));
            runL[i] = fmaf(runL[i], fexp2(runM[i] - nM), s);
            runM[i] = nM;
        }
        __syncthreads();
        if (more) stt68(Bs, pb, tid);
        __syncthreads();
    }
#pragma unroll
    for (int i = 0; i < 4; i++) {
        float M = runM[i], Z = runL[i];
#pragma unroll
        for (int off = 1; off < 8; off <<= 1) {
            float Mo = __shfl_xor_sync(0xffffffffu, M, off, 8);
            float Zo = __shfl_xor_sync(0xffffffffu, Z, off, 8);
            float nM = fmaxf(M, Mo);
            Z = fmaf(Z, fexp2(M - nM), Zo * fexp2(Mo - nM));
            M = nM;
        }
        if (tx == 0) g_mz[(hz * B_ + b) * N_ + n0 + ty * 4 + i] = make_float2(M, Z);
    }
}

// K2b: merge NS partial (M,Z) -> alpha
__global__ void k2b_merge() {
    int i = blockIdx.x * 256 + threadIdx.x;
    if (i < B_ * N_) {
        float2 a = g_mz[i], c = g_mz[B_ * N_ + i];
        float M = fmaxf(a.x, c.x);
        float Z = a.y * fexp2(a.x - M) + c.y * fexp2(c.x - M);
        g_alpha[i] = M + flog2(Z);
    }
}

// K3: attention apply over an n-half, writes partial y_last.
// grid (64,8,NS), block 128, dyn smem 43520
__global__ void __launch_bounds__(128, 4) k3_attn(const float* __restrict__ dummy) {
    extern __shared__ float sm[];
    float* As = sm;            // [32][68] y2 n-tile
    float* Vs = sm + 2176;     // [32][68] y3 n-tile
    float* B1 = sm + 4352;     // [32][68] y1 m-tile
    float* Ps = sm + 6528;     // [64][68] P tile
    int b = blockIdx.y, m0 = blockIdx.x * 64, hz = blockIdx.z;
    int t0 = hz * (N_ / 64 / NS);
    int tid = threadIdx.x, tx = tid & 7, ty = tid >> 3;
    int mg = tid & 15, cg = tid >> 4;
    const float* y1b = g_y1 + b * CI * N_;
    const float* y2b = g_y2 + b * CI * N_;
    const float* y3b = g_y3 + b * CI * N_;
    const float* alb = g_alpha + b * N_;

    float4 p1[4], p2[4], p3[4];
    ldt64(y1b, m0, p1, tid); stt68(B1, p1, tid);
    ldt64(y2b, t0 * 64, p2, tid); stt68(As, p2, tid);
    ldt64(y3b, t0 * 64, p3, tid); stt68(Vs, p3, tid);
    float4 alr = *(const float4*)&alb[t0 * 64 + ty * 4];
    __syncthreads();

    u64 acc[4][2];
#pragma unroll
    for (int i = 0; i < 4; i++) { acc[i][0] = 0ull; acc[i][1] = 0ull; }

    for (int t = t0; t < t0 + N_ / 64 / NS; t++) {
        bool more = t + 1 < t0 + N_ / 64 / NS;
        float4 aln = alr;
        if (more) {
            ldt64(y2b, (t + 1) * 64, p2, tid);
            ldt64(y3b, (t + 1) * 64, p3, tid);
            aln = *(const float4*)&alb[(t + 1) * 64 + ty * 4];
        }
        u64 c2[4][4];
#pragma unroll
        for (int i = 0; i < 4; i++)
#pragma unroll
            for (int j = 0; j < 4; j++) c2[i][j] = 0ull;
        gemm1(As, B1, ty, tx, c2);

        float al[4] = {alr.x, alr.y, alr.z, alr.w};
#pragma unroll
        for (int i = 0; i < 4; i++) {
            float e[8];
            unpack2(c2[i][0], e[0], e[1]); unpack2(c2[i][1], e[2], e[3]);
            unpack2(c2[i][2], e[4], e[5]); unpack2(c2[i][3], e[6], e[7]);
            float4 q0 = make_float4(fexp2(e[0] - al[i]), fexp2(e[1] - al[i]),
                                    fexp2(e[2] - al[i]), fexp2(e[3] - al[i]));
            float4 q1 = make_float4(fexp2(e[4] - al[i]), fexp2(e[5] - al[i]),
                                    fexp2(e[6] - al[i]), fexp2(e[7] - al[i]));
            *(float4*)&Ps[(ty * 4 + i) * 68 + tx * 4]      = q0;
            *(float4*)&Ps[(ty * 4 + i) * 68 + 32 + tx * 4] = q1;
        }
        __syncthreads();   // bar1: Ps ready; all GEMM1 reads done

        // GEMM2: thread = 4ci x 4m; V loaded as float4 over nn (4 nn per chunk).
        const float* vr0 = &Vs[(cg * 4 + 0) * 68];
        const float* vr1 = &Vs[(cg * 4 + 1) * 68];
        const float* vr2 = &Vs[(cg * 4 + 2) * 68];
        const float* vr3 = &Vs[(cg * 4 + 3) * 68];
#pragma unroll 2
        for (int nc = 0; nc < 16; nc++) {
            float4 v0 = *(const float4*)&vr0[nc * 4];
            float4 v1 = *(const float4*)&vr1[nc * 4];
            float4 v2 = *(const float4*)&vr2[nc * 4];
            float4 v3 = *(const float4*)&vr3[nc * 4];
            float a0[4] = {v0.x, v0.y, v0.z, v0.w};
            float a1[4] = {v1.x, v1.y, v1.z, v1.w};
            float a2[4] = {v2.x, v2.y, v2.z, v2.w};
            float a3[4] = {v3.x, v3.y, v3.z, v3.w};
#pragma unroll
            for (int j = 0; j < 4; j++) {
                ulonglong2 pv = *(const ulonglong2*)&Ps[(nc * 4 + j) * 68 + mg * 4];
                u64 w0 = pack2(a0[j], a0[j]), w1 = pack2(a1[j], a1[j]);
                u64 w2 = pack2(a2[j], a2[j]), w3 = pack2(a3[j], a3[j]);
                acc[0][0] = fma2(w0, pv.x, acc[0][0]); acc[0][1] = fma2(w0, pv.y, acc[0][1]);
                acc[1][0] = fma2(w1, pv.x, acc[1][0]); acc[1][1] = fma2(w1, pv.y, acc[1][1]);
                acc[2][0] = fma2(w2, pv.x, acc[2][0]); acc[2][1] = fma2(w2, pv.y, acc[2][1]);
                acc[3][0] = fma2(w3, pv.x, acc[3][0]); acc[3][1] = fma2(w3, pv.y, acc[3][1]);
            }
        }
        if (more) stt68(As, p2, tid);   // safe: all GEMM1 reads done at bar1
        __syncthreads();                // bar2: all GEMM2 reads of Vs/Ps done
        if (more) { stt68(Vs, p3, tid); alr = aln; }
    }

    // write partial y_last tile
    float* pp = g_part + (hz * B_ + b) * CI * N_;
#pragma unroll
    for (int i = 0; i < 4; i++) {
        float4 o;
        unpack2(acc[i][0], o.x, o.y);
        unpack2(acc[i][1], o.z, o.w);
        *(float4*)&pp[(cg * 4 + i) * N_ + m0 + mg * 4] = o;
    }
    (void)dummy;
}

// K4: reduce NS partials + final conv + BN + SiLU + residual. grid (64,8), block 128
__global__ void __launch_bounds__(128) k4_epi(
    const float* __restrict__ w4, const float* __restrict__ s4,
    const float* __restrict__ b4, const float* __restrict__ x,
    float* __restrict__ out) {
    __shared__ float Ys[32 * 68];
    __shared__ float W4t[32 * 260];
    __shared__ float s4s[256], b4s[256];
    int b = blockIdx.y, m0 = blockIdx.x * 64;
    int tid = threadIdx.x;
    int mg = tid & 15, cg = tid >> 4;

    const float* q0 = g_part + b * CI * N_;
    const float* q1 = g_part + (B_ + b) * CI * N_;
#pragma unroll
    for (int s = 0; s < 4; s++) {
        int idx = tid + s * 128;               // float4 index within [32][64]
        int ci = idx >> 4, off = (idx & 15) << 2;
        float4 u = *(const float4*)&q0[ci * N_ + m0 + off];
        float4 v = *(const float4*)&q1[ci * N_ + m0 + off];
        u.x += v.x; u.y += v.y; u.z += v.z; u.w += v.w;
        *(float4*)&Ys[ci * 68 + off] = u;
    }
    for (int idx = tid; idx < C_ * CI; idx += 128) {
        int co = idx >> 5, k = idx & 31;
        W4t[k * 260 + co] = w4[idx];
    }
    s4s[tid] = s4[tid]; s4s[tid + 128] = s4[tid + 128];
    b4s[tid] = b4[tid]; b4s[tid + 128] = b4[tid + 128];
    __syncthreads();

#pragma unroll
    for (int pass = 0; pass < 2; pass++) {
        int co0 = cg * 16 + pass * 128;
        u64 e2[16][2];
#pragma unroll
        for (int j = 0; j < 16; j++) { e2[j][0] = 0ull; e2[j][1] = 0ull; }
#pragma unroll 4
        for (int k = 0; k < CI; k++) {
            ulonglong2 ym = *(const ulonglong2*)&Ys[k * 68 + mg * 4];
#pragma unroll
            for (int q = 0; q < 4; q++) {
                float4 wq = *(const float4*)&W4t[k * 260 + co0 + q * 4];
                u64 w0 = pack2(wq.x, wq.x), w1 = pack2(wq.y, wq.y);
                u64 w2 = pack2(wq.z, wq.z), w3 = pack2(wq.w, wq.w);
                e2[q * 4 + 0][0] = fma2(w0, ym.x, e2[q * 4 + 0][0]);
                e2[q * 4 + 0][1] = fma2(w0, ym.y, e2[q * 4 + 0][1]);
                e2[q * 4 + 1][0] = fma2(w1, ym.x, e2[q * 4 + 1][0]);
                e2[q * 4 + 1][1] = fma2(w1, ym.y, e2[q * 4 + 1][1]);
                e2[q * 4 + 2][0] = fma2(w2, ym.x, e2[q * 4 + 2][0]);
                e2[q * 4 + 2][1] = fma2(w2, ym.y, e2[q * 4 + 2][1]);
                e2[q * 4 + 3][0] = fma2(w3, ym.x, e2[q * 4 + 3][0]);
                e2[q * 4 + 3][1] = fma2(w3, ym.y, e2[q * 4 + 3][1]);
            }
        }
#pragma unroll
        for (int j = 0; j < 16; j++) {
            int co = co0 + j;
            float sc = s4s[co], bi = b4s[co];
            float v0, v1, v2, v3;
            unpack2(e2[j][0], v0, v1); unpack2(e2[j][1], v2, v3);
            float y0 = fmaf(v0, sc, bi), y1 = fmaf(v1, sc, bi);
            float y2v = fmaf(v2, sc, bi), y3v = fmaf(v3, sc, bi);
            int off = b * C_ * N_ + co * N_ + m0 + mg * 4;
            float4 xr = *(const float4*)&x[off];
            float4 ov;
            ov.x = fmaf(y0,  frcp(1.f + fexp2(-y0 * L2E)),  xr.x);
            ov.y = fmaf(y1,  frcp(1.f + fexp2(-y1 * L2E)),  xr.y);
            ov.z = fmaf(y2v, frcp(1.f + fexp2(-y2v * L2E)), xr.z);
            ov.w = fmaf(y3v, frcp(1.f + fexp2(-y3v * L2E)), xr.w);
            *(float4*)&out[off] = ov;
        }
    }
}

extern "C" void kernel_launch(void* const* d_in, const int* in_sizes, int n_in,
                              void* d_out, int out_size) {
    (void)in_sizes; (void)n_in; (void)out_size;
    const float* x  = (const float*)d_in[0];
    const float* w1 = (const float*)d_in[1];
    const float* s1 = (const float*)d_in[2];
    const float* b1 = (const float*)d_in[3];
    const float* w2 = (const float*)d_in[4];
    const float* s2 = (const float*)d_in[5];
    const float* b2 = (const float*)d_in[6];
    const float* w3 = (const float*)d_in[7];
    const float* s3 = (const float*)d_in[8];
    const float* b3 = (const float*)d_in[9];
    const float* w4 = (const float*)d_in[10];
    const float* s4 = (const float*)d_in[11];
    const float* b4 = (const float*)d_in[12];
    float* out = (float*)d_out;

    cudaFuncSetAttribute(k1_conv, cudaFuncAttributeMaxDynamicSharedMemorySize, 99072);
    cudaFuncSetAttribute(k3_attn, cudaFuncAttributeMaxDynamicSharedMemorySize, 43520);

    k0_prep<<<96, 256>>>(w1, w2, w3);
    k1_conv<<<128, 256, 99072>>>(x, s1, b1, s2, b2, s3, b3);
    k2_stats<<<dim3(64, B_, NS), 128>>>();
    k2b_merge<<<(B_ * N_ + 255) / 256, 256>>>();
    k3_attn<<<dim3(64, B_, NS), 128, 43520>>>(x);
    k4_epi<<<dim3(64, B_), 128>>>(w4, s4, b4, x, out);
}

// round 10
// speedup vs baseline: 3.3639x; 1.9775x over previous
#include <cuda_runtime.h>
#include <cuda_bf16.h>
#include <cstdint>

#define DEV_INLINE __device__ __forceinline__
typedef unsigned long long u64;
typedef uint32_t u32;

constexpr int B_ = 8;
constexpr int C_ = 256;
constexpr int CI = 32;
constexpr int N_ = 4096;
constexpr float L2E = 1.4426950408889634f;
constexpr int STR = 144;   // smem operand row stride (bytes)

__device__ __align__(128) float g_alpha[B_ * N_];
__device__ __align__(128) float g_wAll[C_ * 96];
__device__ __align__(128) float g_part[2 * B_ * CI * N_];
__device__ __align__(128) float2 g_mz[2 * B_ * N_];
__device__ __align__(128) __nv_bfloat16 g_y1b[(size_t)B_ * N_ * 64];  // [pos][32hi|32lo]
__device__ __align__(128) __nv_bfloat16 g_y2b[(size_t)B_ * N_ * 64];  // pre-scaled log2e
__device__ __align__(128) __nv_bfloat16 g_y3h[(size_t)B_ * CI * N_];  // [ci][n] hi
__device__ __align__(128) __nv_bfloat16 g_y3l[(size_t)B_ * CI * N_];  // lo

DEV_INLINE float fexp2(float v) { float y; asm("ex2.approx.ftz.f32 %0, %1;" : "=f"(y) : "f"(v)); return y; }
DEV_INLINE float flog2(float v) { float y; asm("lg2.approx.ftz.f32 %0, %1;" : "=f"(y) : "f"(v)); return y; }
DEV_INLINE float frcp(float v)  { float y; asm("rcp.approx.ftz.f32 %0, %1;" : "=f"(y) : "f"(v)); return y; }
DEV_INLINE u64 pack2(float lo, float hi) {
    u64 r; asm("mov.b64 %0, {%1,%2};" : "=l"(r) : "r"(__float_as_uint(lo)), "r"(__float_as_uint(hi)));
    return r;
}
DEV_INLINE void unpack2(u64 v, float& lo, float& hi) {
    unsigned a, b; asm("mov.b64 {%0,%1}, %2;" : "=r"(a), "=r"(b) : "l"(v));
    lo = __uint_as_float(a); hi = __uint_as_float(b);
}
DEV_INLINE u64 fma2(u64 a, u64 b, u64 c) {
    u64 d; asm("fma.rn.f32x2 %0, %1, %2, %3;" : "=l"(d) : "l"(a), "l"(b), "l"(c));
    return d;
}
DEV_INLINE void split2(float2 f, unsigned& h, unsigned& l) {
    __nv_bfloat162 hb = __float22bfloat162_rn(f);
    h = *(unsigned*)&hb;
    float2 hf = __bfloat1622float2(hb);
    __nv_bfloat162 lb = __float22bfloat162_rn(make_float2(f.x - hf.x, f.y - hf.y));
    l = *(unsigned*)&lb;
}
DEV_INLINE u32 smem_u32(const void* p) {
    u32 a; asm("{ .reg .u64 t; cvta.to.shared.u64 t, %1; cvt.u32.u64 %0, t; }" : "=r"(a) : "l"(p));
    return a;
}
DEV_INLINE void ldsm4(u32* r, u32 a) {
    asm volatile("ldmatrix.sync.aligned.m8n8.x4.shared.b16 {%0,%1,%2,%3}, [%4];"
                 : "=r"(r[0]), "=r"(r[1]), "=r"(r[2]), "=r"(r[3]) : "r"(a));
}
DEV_INLINE void ldsm2(u32* r, u32 a) {
    asm volatile("ldmatrix.sync.aligned.m8n8.x2.shared.b16 {%0,%1}, [%2];"
                 : "=r"(r[0]), "=r"(r[1]) : "r"(a));
}
DEV_INLINE void mma16816(float* d, const u32* a, const u32* b) {
    asm volatile("mma.sync.aligned.m16n8k16.row.col.f32.bf16.bf16.f32 "
        "{%0,%1,%2,%3},{%4,%5,%6,%7},{%8,%9},{%0,%1,%2,%3};"
        : "+f"(d[0]), "+f"(d[1]), "+f"(d[2]), "+f"(d[3])
        : "r"(a[0]), "r"(a[1]), "r"(a[2]), "r"(a[3]), "r"(b[0]), "r"(b[1]));
}
DEV_INLINE u32 cvt2(float lo, float hi) {   // pack {hi:lo} bf16x2
    u32 r; asm("cvt.rn.bf16x2.f32 %0, %1, %2;" : "=r"(r) : "f"(hi), "f"(lo));
    return r;
}
DEV_INLINE float lo_f(u32 h) { return __uint_as_float(h << 16); }
DEV_INLINE float hi_f(u32 h) { return __uint_as_float(h & 0xffff0000u); }

// load A-side frags (rows of [32hi|32lo]) once: Ah/Al [mb][kstep][4]
DEV_INLINE void load_afrags(u32 base, int w, int L, u32 Ah[2][2][4], u32 Al[2][2][4]) {
#pragma unroll
    for (int mb = 0; mb < 2; mb++) {
        u32 a = base + (u32)((w * 32 + mb * 16 + (L & 15)) * STR) + (u32)((L >> 4) * 16);
#pragma unroll
        for (int k = 0; k < 2; k++) {
            ldsm4(Ah[mb][k], a + k * 32);
            ldsm4(Al[mb][k], a + 64 + k * 32);
        }
    }
}

// ---------------------------------------------------------------------------
__global__ void k0_prep(const float* __restrict__ w1, const float* __restrict__ w2,
                        const float* __restrict__ w3) {
    int i = blockIdx.x * 256 + threadIdx.x;
    if (i < C_ * 96) {
        int k = i / 96, j = i - k * 96;
        int br = j >> 5, co = j & 31;
        const float* w = br == 0 ? w1 : br == 1 ? w2 : w3;
        g_wAll[i] = w[co * C_ + k];
    }
}

// K1: three branch convs fused; emits bf16 split operands. grid 128, block 256.
__global__ void __launch_bounds__(256, 1) k1_conv(
    const float* __restrict__ x,
    const float* __restrict__ s1, const float* __restrict__ b1,
    const float* __restrict__ s2, const float* __restrict__ b2,
    const float* __restrict__ s3, const float* __restrict__ b3) {
    extern __shared__ float sm[];
    float* wAll = sm;
    float* sAll = sm + 24576;
    float* bAll = sAll + 96;
    int tid = threadIdx.x;
    const float4* wsrc = (const float4*)g_wAll;
#pragma unroll
    for (int s = 0; s < 24; s++) ((float4*)wAll)[tid + s * 256] = wsrc[tid + s * 256];
    if (tid < 96) {
        sAll[tid] = tid < 32 ? s1[tid] : tid < 64 ? s2[tid - 32] : s3[tid - 64];
        bAll[tid] = tid < 32 ? b1[tid] : tid < 64 ? b2[tid - 32] : b3[tid - 64];
    }
    __syncthreads();
    int gpos = blockIdx.x * 256 + tid;
    int b = gpos >> 12, m = gpos & (N_ - 1);
    const float* xp = x + b * C_ * N_ + m;
    u64 acc2[48];
#pragma unroll
    for (int i = 0; i < 48; i++) acc2[i] = 0ull;
#pragma unroll 2
    for (int k = 0; k < C_; k++) {
        float xv = __ldg(&xp[k * N_]);
        u64 xq = pack2(xv, xv);
        const ulonglong2* wk = (const ulonglong2*)&wAll[k * 96];
#pragma unroll
        for (int t = 0; t < 24; t++) {
            ulonglong2 wv = wk[t];
            acc2[2 * t]     = fma2(xq, wv.x, acc2[2 * t]);
            acc2[2 * t + 1] = fma2(xq, wv.y, acc2[2 * t + 1]);
        }
    }
#pragma unroll
    for (int br = 0; br < 2; br++) {
        unsigned hh[16], ll[16];
        float mulf = br ? L2E : 1.f;
#pragma unroll
        for (int p = 0; p < 16; p++) {
            float v0, v1;
            unpack2(acc2[br * 16 + p], v0, v1);
            float y0 = fmaf(v0, sAll[br * 32 + 2 * p],     bAll[br * 32 + 2 * p]);
            float y1 = fmaf(v1, sAll[br * 32 + 2 * p + 1], bAll[br * 32 + 2 * p + 1]);
            y0 = y0 * frcp(1.f + fexp2(-y0 * L2E)) * mulf;
            y1 = y1 * frcp(1.f + fexp2(-y1 * L2E)) * mulf;
            split2(make_float2(y0, y1), hh[p], ll[p]);
        }
        uint4* d = (uint4*)((br ? g_y2b : g_y1b) + (size_t)gpos * 64);
#pragma unroll
        for (int j = 0; j < 4; j++) d[j]     = make_uint4(hh[4 * j], hh[4 * j + 1], hh[4 * j + 2], hh[4 * j + 3]);
#pragma unroll
        for (int j = 0; j < 4; j++) d[4 + j] = make_uint4(ll[4 * j], ll[4 * j + 1], ll[4 * j + 2], ll[4 * j + 3]);
    }
#pragma unroll
    for (int p = 0; p < 16; p++) {
        float v0, v1;
        unpack2(acc2[32 + p], v0, v1);
        float y0 = fmaf(v0, sAll[64 + 2 * p],     bAll[64 + 2 * p]);
        float y1 = fmaf(v1, sAll[64 + 2 * p + 1], bAll[64 + 2 * p + 1]);
        y0 = y0 * frcp(1.f + fexp2(-y0 * L2E));
        y1 = y1 * frcp(1.f + fexp2(-y1 * L2E));
        size_t base = ((size_t)b * CI + 2 * p) * N_ + m;
        __nv_bfloat16 h0 = __float2bfloat16(y0);
        __nv_bfloat16 h1 = __float2bfloat16(y1);
        g_y3h[base] = h0;       g_y3l[base] = __float2bfloat16(y0 - __bfloat162float(h0));
        g_y3h[base + N_] = h1;  g_y3l[base + N_] = __float2bfloat16(y1 - __bfloat162float(h1));
    }
}

// K2t: softmax stats via mma.sync. grid (32, B, 2), block 128.
__global__ void __launch_bounds__(128) k2t() {
    __shared__ char An[128 * STR + 64 * STR];
    char* Bm = An + 128 * STR;
    u32 sbA = smem_u32(An), sbB = sbA + 128 * STR;
    int tid = threadIdx.x, w = tid >> 5, L = tid & 31;
    int b = blockIdx.y, n0 = blockIdx.x * 128, hz = blockIdx.z;
    {
        const uint4* s = (const uint4*)(g_y2b + ((size_t)b * N_ + n0 + tid) * 64);
        uint4* d = (uint4*)(An + tid * STR);
#pragma unroll
        for (int j = 0; j < 8; j++) d[j] = s[j];
    }
    __syncthreads();
    u32 Ah[2][2][4], Al[2][2][4];
    load_afrags(sbA, w, L, Ah, Al);

    float M[2][2], Z[2][2];
#pragma unroll
    for (int i = 0; i < 2; i++)
#pragma unroll
        for (int j = 0; j < 2; j++) { M[i][j] = -1.0e30f; Z[i][j] = 0.f; }

    for (int tt = 0; tt < 32; tt++) {
        int mc = hz * 2048 + tt * 64;
        {
            int r = tid >> 1, h = tid & 1;
            const uint4* s = (const uint4*)(g_y1b + ((size_t)b * N_ + mc + r) * 64 + h * 32);
            uint4* d = (uint4*)(Bm + r * STR + h * 64);
            d[0] = s[0]; d[1] = s[1]; d[2] = s[2]; d[3] = s[3];
        }
        __syncthreads();
        float s_[2][8][4];
#pragma unroll
        for (int i = 0; i < 2; i++)
#pragma unroll
            for (int j = 0; j < 8; j++)
#pragma unroll
                for (int q = 0; q < 4; q++) s_[i][j][q] = 0.f;
#pragma unroll
        for (int j = 0; j < 8; j++) {
            u32 bb = sbB + (u32)((j * 8 + (L & 7)) * STR) + (u32)(((L >> 3) & 1) * 16);
            u32 Bh0[2], Bh1[2], Bl0[2], Bl1[2];
            ldsm2(Bh0, bb);      ldsm2(Bh1, bb + 32);
            ldsm2(Bl0, bb + 64); ldsm2(Bl1, bb + 96);
#pragma unroll
            for (int mb = 0; mb < 2; mb++) {
                mma16816(s_[mb][j], Ah[mb][0], Bh0); mma16816(s_[mb][j], Ah[mb][1], Bh1);
                mma16816(s_[mb][j], Al[mb][0], Bh0); mma16816(s_[mb][j], Al[mb][1], Bh1);
                mma16816(s_[mb][j], Ah[mb][0], Bl0); mma16816(s_[mb][j], Ah[mb][1], Bl1);
            }
        }
        __syncthreads();
#pragma unroll
        for (int mb = 0; mb < 2; mb++)
#pragma unroll
            for (int rh = 0; rh < 2; rh++) {
                float mx = -1.0e30f;
#pragma unroll
                for (int j = 0; j < 8; j++)
                    mx = fmaxf(mx, fmaxf(s_[mb][j][rh * 2], s_[mb][j][rh * 2 + 1]));
                float nM = fmaxf(M[mb][rh], mx), ss = 0.f;
#pragma unroll
                for (int j = 0; j < 8; j++)
                    ss += fexp2(s_[mb][j][rh * 2] - nM) + fexp2(s_[mb][j][rh * 2 + 1] - nM);
                Z[mb][rh] = fmaf(Z[mb][rh], fexp2(M[mb][rh] - nM), ss);
                M[mb][rh] = nM;
            }
    }
#pragma unroll
    for (int mb = 0; mb < 2; mb++)
#pragma unroll
        for (int rh = 0; rh < 2; rh++) {
            float m = M[mb][rh], z = Z[mb][rh];
#pragma unroll
            for (int off = 1; off < 4; off <<= 1) {
                float mo = __shfl_xor_sync(0xffffffffu, m, off);
                float zo = __shfl_xor_sync(0xffffffffu, z, off);
                float nM = fmaxf(m, mo);
                z = fmaf(z, fexp2(m - nM), zo * fexp2(mo - nM));
                m = nM;
            }
            if ((L & 3) == 0)
                g_mz[(size_t)(hz * B_ + b) * N_ + n0 + w * 32 + mb * 16 + rh * 8 + (L >> 2)] =
                    make_float2(m, z);
        }
}

__global__ void k2b_merge() {
    int i = blockIdx.x * 256 + threadIdx.x;
    if (i < B_ * N_) {
        float2 a = g_mz[i], c = g_mz[B_ * N_ + i];
        float M = fmaxf(a.x, c.x);
        float Z = a.y * fexp2(a.x - M) + c.y * fexp2(c.x - M);
        g_alpha[i] = M + flog2(Z);
    }
}

// K3t: attention apply via mma.sync + FA2 register P. grid (32, B, 2), block 128.
__global__ void __launch_bounds__(128) k3t() {
    __shared__ char SM[128 * STR + 64 * STR + 64 * STR + 256];
    char* A1 = SM;
    char* Qs = SM + 128 * STR;
    char* Vh = Qs + 64 * STR;
    char* Vl = Vh + 32 * STR;
    float* alp = (float*)(Vl + 32 * STR);
    u32 sbA = smem_u32(A1), sbQ = sbA + 128 * STR, sbVh = sbQ + 64 * STR, sbVl = sbVh + 32 * STR;
    int tid = threadIdx.x, w = tid >> 5, L = tid & 31;
    int b = blockIdx.y, m0 = blockIdx.x * 128, hz = blockIdx.z;
    {
        const uint4* s = (const uint4*)(g_y1b + ((size_t)b * N_ + m0 + tid) * 64);
        uint4* d = (uint4*)(A1 + tid * STR);
#pragma unroll
        for (int j = 0; j < 8; j++) d[j] = s[j];
    }
    __syncthreads();
    u32 Ah[2][2][4], Al[2][2][4];
    load_afrags(sbA, w, L, Ah, Al);

    float d2[2][4][4];
#pragma unroll
    for (int i = 0; i < 2; i++)
#pragma unroll
        for (int j = 0; j < 4; j++)
#pragma unroll
            for (int q = 0; q < 4; q++) d2[i][j][q] = 0.f;

    for (int tt = 0; tt < 32; tt++) {
        int nc = hz * 2048 + tt * 64;
        {
            int r = tid >> 1, h = tid & 1;
            const uint4* s = (const uint4*)(g_y2b + ((size_t)b * N_ + nc + r) * 64 + h * 32);
            uint4* d = (uint4*)(Qs + r * STR + h * 64);
            d[0] = s[0]; d[1] = s[1]; d[2] = s[2]; d[3] = s[3];
            int ci = tid >> 2, q = tid & 3;
            const uint4* vh = (const uint4*)(g_y3h + ((size_t)b * CI + ci) * N_ + nc + q * 16);
            const uint4* vl = (const uint4*)(g_y3l + ((size_t)b * CI + ci) * N_ + nc + q * 16);
            uint4* dh = (uint4*)(Vh + ci * STR + q * 32);
            uint4* dl = (uint4*)(Vl + ci * STR + q * 32);
            dh[0] = vh[0]; dh[1] = vh[1];
            dl[0] = vl[0]; dl[1] = vl[1];
            if (tid < 16) ((float4*)alp)[tid] = ((const float4*)(g_alpha + (size_t)b * N_ + nc))[tid];
        }
        __syncthreads();
#pragma unroll
        for (int nbp = 0; nbp < 4; nbp++) {
            u32 Vhf[4][2], Vlf[4][2];
#pragma unroll
            for (int cb = 0; cb < 4; cb++) {
                u32 va = (u32)((cb * 8 + (L & 7)) * STR) + (u32)(nbp * 32 + ((L >> 3) & 1) * 16);
                ldsm2(Vhf[cb], sbVh + va);
                ldsm2(Vlf[cb], sbVl + va);
            }
            u32 Bh[2][2][2], Bl[2][2][2];
#pragma unroll
            for (int nb2 = 0; nb2 < 2; nb2++) {
                u32 qa = sbQ + (u32)(((nbp * 2 + nb2) * 8 + (L & 7)) * STR) + (u32)(((L >> 3) & 1) * 16);
                ldsm2(Bh[nb2][0], qa);      ldsm2(Bh[nb2][1], qa + 32);
                ldsm2(Bl[nb2][0], qa + 64); ldsm2(Bl[nb2][1], qa + 96);
            }
#pragma unroll
            for (int mb = 0; mb < 2; mb++) {
                float s_[2][4];
#pragma unroll
                for (int nb2 = 0; nb2 < 2; nb2++) {
#pragma unroll
                    for (int q = 0; q < 4; q++) s_[nb2][q] = 0.f;
                    mma16816(s_[nb2], Ah[mb][0], Bh[nb2][0]); mma16816(s_[nb2], Ah[mb][1], Bh[nb2][1]);
                    mma16816(s_[nb2], Al[mb][0], Bh[nb2][0]); mma16816(s_[nb2], Al[mb][1], Bh[nb2][1]);
                    mma16816(s_[nb2], Ah[mb][0], Bl[nb2][0]); mma16816(s_[nb2], Ah[mb][1], Bl[nb2][1]);
                }
                u32 ph[4], pl[4];
#pragma unroll
                for (int nb2 = 0; nb2 < 2; nb2++) {
                    int cn = (nbp * 2 + nb2) * 8 + 2 * (L & 3);
                    float a0 = alp[cn], a1 = alp[cn + 1];
                    float e0 = fexp2(s_[nb2][0] - a0), e1 = fexp2(s_[nb2][1] - a1);
                    float e2 = fexp2(s_[nb2][2] - a0), e3 = fexp2(s_[nb2][3] - a1);
                    u32 h01 = cvt2(e0, e1), h23 = cvt2(e2, e3);
                    ph[nb2 * 2] = h01; ph[nb2 * 2 + 1] = h23;
                    pl[nb2 * 2]     = cvt2(e0 - lo_f(h01), e1 - hi_f(h01));
                    pl[nb2 * 2 + 1] = cvt2(e2 - lo_f(h23), e3 - hi_f(h23));
                }
#pragma unroll
                for (int cb = 0; cb < 4; cb++) {
                    mma16816(d2[mb][cb], ph, Vhf[cb]);
                    mma16816(d2[mb][cb], pl, Vhf[cb]);
                    mma16816(d2[mb][cb], ph, Vlf[cb]);
                }
            }
        }
        __syncthreads();
    }
    float* pp = g_part + (size_t)(hz * B_ + b) * CI * N_;
#pragma unroll
    for (int mb = 0; mb < 2; mb++)
#pragma unroll
        for (int cb = 0; cb < 4; cb++) {
            int row = m0 + w * 32 + mb * 16 + (L >> 2);
            int ci0 = cb * 8 + 2 * (L & 3);
            pp[(size_t)ci0 * N_ + row]           = d2[mb][cb][0];
            pp[(size_t)(ci0 + 1) * N_ + row]     = d2[mb][cb][1];
            pp[(size_t)ci0 * N_ + row + 8]       = d2[mb][cb][2];
            pp[(size_t)(ci0 + 1) * N_ + row + 8] = d2[mb][cb][3];
        }
}

// K4: reduce 2 partials + final conv + BN + SiLU + residual. grid (64,8), block 128
__global__ void __launch_bounds__(128) k4_epi(
    const float* __restrict__ w4, const float* __restrict__ s4,
    const float* __restrict__ b4, const float* __restrict__ x,
    float* __restrict__ out) {
    __shared__ float Ys[32 * 68];
    __shared__ float W4t[32 * 260];
    __shared__ float s4s[256], b4s[256];
    int b = blockIdx.y, m0 = blockIdx.x * 64;
    int tid = threadIdx.x;
    int mg = tid & 15, cg = tid >> 4;
    const float* q0 = g_part + (size_t)b * CI * N_;
    const float* q1 = g_part + (size_t)(B_ + b) * CI * N_;
#pragma unroll
    for (int s = 0; s < 4; s++) {
        int idx = tid + s * 128;
        int ci = idx >> 4, off = (idx & 15) << 2;
        float4 u = *(const float4*)&q0[ci * N_ + m0 + off];
        float4 v = *(const float4*)&q1[ci * N_ + m0 + off];
        u.x += v.x; u.y += v.y; u.z += v.z; u.w += v.w;
        *(float4*)&Ys[ci * 68 + off] = u;
    }
    for (int idx = tid; idx < C_ * CI; idx += 128) {
        int co = idx >> 5, k = idx & 31;
        W4t[k * 260 + co] = w4[idx];
    }
    s4s[tid] = s4[tid]; s4s[tid + 128] = s4[tid + 128];
    b4s[tid] = b4[tid]; b4s[tid + 128] = b4[tid + 128];
    __syncthreads();
#pragma unroll
    for (int pass = 0; pass < 2; pass++) {
        int co0 = cg * 16 + pass * 128;
        u64 e2[16][2];
#pragma unroll
        for (int j = 0; j < 16; j++) { e2[j][0] = 0ull; e2[j][1] = 0ull; }
#pragma unroll 4
        for (int k = 0; k < CI; k++) {
            ulonglong2 ym = *(const ulonglong2*)&Ys[k * 68 + mg * 4];
#pragma unroll
            for (int q = 0; q < 4; q++) {
                float4 wq = *(const float4*)&W4t[k * 260 + co0 + q * 4];
                u64 w0 = pack2(wq.x, wq.x), w1 = pack2(wq.y, wq.y);
                u64 w2 = pack2(wq.z, wq.z), w3 = pack2(wq.w, wq.w);
                e2[q * 4 + 0][0] = fma2(w0, ym.x, e2[q * 4 + 0][0]);
                e2[q * 4 + 0][1] = fma2(w0, ym.y, e2[q * 4 + 0][1]);
                e2[q * 4 + 1][0] = fma2(w1, ym.x, e2[q * 4 + 1][0]);
                e2[q * 4 + 1][1] = fma2(w1, ym.y, e2[q * 4 + 1][1]);
                e2[q * 4 + 2][0] = fma2(w2, ym.x, e2[q * 4 + 2][0]);
                e2[q * 4 + 2][1] = fma2(w2, ym.y, e2[q * 4 + 2][1]);
                e2[q * 4 + 3][0] = fma2(w3, ym.x, e2[q * 4 + 3][0]);
                e2[q * 4 + 3][1] = fma2(w3, ym.y, e2[q * 4 + 3][1]);
            }
        }
#pragma unroll
        for (int j = 0; j < 16; j++) {
            int co = co0 + j;
            float sc = s4s[co], bi = b4s[co];
            float v0, v1, v2, v3;
            unpack2(e2[j][0], v0, v1); unpack2(e2[j][1], v2, v3);
            float y0 = fmaf(v0, sc, bi), y1 = fmaf(v1, sc, bi);
            float y2v = fmaf(v2, sc, bi), y3v = fmaf(v3, sc, bi);
            int off = b * C_ * N_ + co * N_ + m0 + mg * 4;
            float4 xr = *(const float4*)&x[off];
            float4 ov;
            ov.x = fmaf(y0,  frcp(1.f + fexp2(-y0 * L2E)),  xr.x);
            ov.y = fmaf(y1,  frcp(1.f + fexp2(-y1 * L2E)),  xr.y);
            ov.z = fmaf(y2v, frcp(1.f + fexp2(-y2v * L2E)), xr.z);
            ov.w = fmaf(y3v, frcp(1.f + fexp2(-y3v * L2E)), xr.w);
            *(float4*)&out[off] = ov;
        }
    }
}

extern "C" void kernel_launch(void* const* d_in, const int* in_sizes, int n_in,
                              void* d_out, int out_size) {
    (void)in_sizes; (void)n_in; (void)out_size;
    const float* x  = (const float*)d_in[0];
    const float* w1 = (const float*)d_in[1];
    const float* s1 = (const float*)d_in[2];
    const float* b1 = (const float*)d_in[3];
    const float* w2 = (const float*)d_in[4];
    const float* s2 = (const float*)d_in[5];
    const float* b2 = (const float*)d_in[6];
    const float* w3 = (const float*)d_in[7];
    const float* s3 = (const float*)d_in[8];
    const float* b3 = (const float*)d_in[9];
    const float* w4 = (const float*)d_in[10];
    const float* s4 = (const float*)d_in[11];
    const float* b4 = (const float*)d_in[12];
    float* out = (float*)d_out;

    cudaFuncSetAttribute(k1_conv, cudaFuncAttributeMaxDynamicSharedMemorySize, 99072);

    k0_prep<<<96, 256>>>(w1, w2, w3);
    k1_conv<<<128, 256, 99072>>>(x, s1, b1, s2, b2, s3, b3);
    k2t<<<dim3(32, B_, 2), 128>>>();
    k2b_merge<<<(B_ * N_ + 255) / 256, 256>>>();
    k3t<<<dim3(32, B_, 2), 128>>>();
    k4_epi<<<dim3(64, B_), 128>>>(w4, s4, b4, x, out);
}

// round 11
// speedup vs baseline: 3.9406x; 1.1714x over previous
#include <cuda_runtime.h>
#include <cuda_bf16.h>
#include <cstdint>

#define DEV_INLINE __device__ __forceinline__
typedef unsigned long long u64;
typedef uint32_t u32;

constexpr int B_ = 8;
constexpr int C_ = 256;
constexpr int CI = 32;
constexpr int N_ = 4096;
constexpr float L2E = 1.4426950408889634f;
constexpr int STR = 144;   // smem operand row stride (bytes)

__device__ __align__(128) float g_alpha[B_ * N_];
__device__ __align__(128) float g_wAll[C_ * 96];
__device__ __align__(128) float g_part[2 * B_ * CI * N_];
__device__ __align__(128) float2 g_mz[2 * B_ * N_];
__device__ __align__(128) __nv_bfloat16 g_y1b[(size_t)B_ * N_ * 64];  // [pos][32hi|32lo]
__device__ __align__(128) __nv_bfloat16 g_y2b[(size_t)B_ * N_ * 64];  // pre-scaled log2e
__device__ __align__(128) __nv_bfloat16 g_y3h[(size_t)B_ * CI * N_];  // [ci][n] hi

DEV_INLINE float fexp2(float v) { float y; asm("ex2.approx.ftz.f32 %0, %1;" : "=f"(y) : "f"(v)); return y; }
DEV_INLINE float flog2(float v) { float y; asm("lg2.approx.ftz.f32 %0, %1;" : "=f"(y) : "f"(v)); return y; }
DEV_INLINE float frcp(float v)  { float y; asm("rcp.approx.ftz.f32 %0, %1;" : "=f"(y) : "f"(v)); return y; }
DEV_INLINE u64 pack2(float lo, float hi) {
    u64 r; asm("mov.b64 %0, {%1,%2};" : "=l"(r) : "r"(__float_as_uint(lo)), "r"(__float_as_uint(hi)));
    return r;
}
DEV_INLINE void unpack2(u64 v, float& lo, float& hi) {
    unsigned a, b; asm("mov.b64 {%0,%1}, %2;" : "=r"(a), "=r"(b) : "l"(v));
    lo = __uint_as_float(a); hi = __uint_as_float(b);
}
DEV_INLINE u64 fma2(u64 a, u64 b, u64 c) {
    u64 d; asm("fma.rn.f32x2 %0, %1, %2, %3;" : "=l"(d) : "l"(a), "l"(b), "l"(c));
    return d;
}
DEV_INLINE void split2(float2 f, unsigned& h, unsigned& l) {
    __nv_bfloat162 hb = __float22bfloat162_rn(f);
    h = *(unsigned*)&hb;
    float2 hf = __bfloat1622float2(hb);
    __nv_bfloat162 lb = __float22bfloat162_rn(make_float2(f.x - hf.x, f.y - hf.y));
    l = *(unsigned*)&lb;
}
DEV_INLINE u32 smem_u32(const void* p) {
    u32 a; asm("{ .reg .u64 t; cvta.to.shared.u64 t, %1; cvt.u32.u64 %0, t; }" : "=r"(a) : "l"(p));
    return a;
}
DEV_INLINE void ldsm4(u32* r, u32 a) {
    asm volatile("ldmatrix.sync.aligned.m8n8.x4.shared.b16 {%0,%1,%2,%3}, [%4];"
                 : "=r"(r[0]), "=r"(r[1]), "=r"(r[2]), "=r"(r[3]) : "r"(a));
}
DEV_INLINE void ldsm2(u32* r, u32 a) {
    asm volatile("ldmatrix.sync.aligned.m8n8.x2.shared.b16 {%0,%1}, [%2];"
                 : "=r"(r[0]), "=r"(r[1]) : "r"(a));
}
DEV_INLINE void mma16816(float* d, const u32* a, const u32* b) {
    asm volatile("mma.sync.aligned.m16n8k16.row.col.f32.bf16.bf16.f32 "
        "{%0,%1,%2,%3},{%4,%5,%6,%7},{%8,%9},{%0,%1,%2,%3};"
        : "+f"(d[0]), "+f"(d[1]), "+f"(d[2]), "+f"(d[3])
        : "r"(a[0]), "r"(a[1]), "r"(a[2]), "r"(a[3]), "r"(b[0]), "r"(b[1]));
}
DEV_INLINE u32 cvt2(float lo, float hi) {   // pack {hi:lo} bf16x2
    u32 r; asm("cvt.rn.bf16x2.f32 %0, %1, %2;" : "=r"(r) : "f"(hi), "f"(lo));
    return r;
}
DEV_INLINE float lo_f(u32 h) { return __uint_as_float(h << 16); }
DEV_INLINE float hi_f(u32 h) { return __uint_as_float(h & 0xffff0000u); }

// load A-side frags (rows of [32hi|32lo]) once: Ah/Al [mb][kstep][4]
DEV_INLINE void load_afrags(u32 base, int w, int L, u32 Ah[2][2][4], u32 Al[2][2][4]) {
#pragma unroll
    for (int mb = 0; mb < 2; mb++) {
        u32 a = base + (u32)((w * 32 + mb * 16 + (L & 15)) * STR) + (u32)((L >> 4) * 16);
#pragma unroll
        for (int k = 0; k < 2; k++) {
            ldsm4(Ah[mb][k], a + k * 32);
            ldsm4(Al[mb][k], a + 64 + k * 32);
        }
    }
}

// ---------------------------------------------------------------------------
__global__ void k0_prep(const float* __restrict__ w1, const float* __restrict__ w2,
                        const float* __restrict__ w3) {
    int i = blockIdx.x * 256 + threadIdx.x;
    if (i < C_ * 96) {
        int k = i / 96, j = i - k * 96;
        int br = j >> 5, co = j & 31;
        const float* w = br == 0 ? w1 : br == 1 ? w2 : w3;
        g_wAll[i] = w[co * C_ + k];
    }
}

// K1: three branch convs fused; emits bf16 split operands. grid 128, block 256.
__global__ void __launch_bounds__(256, 1) k1_conv(
    const float* __restrict__ x,
    const float* __restrict__ s1, const float* __restrict__ b1,
    const float* __restrict__ s2, const float* __restrict__ b2,
    const float* __restrict__ s3, const float* __restrict__ b3) {
    extern __shared__ float sm[];
    float* wAll = sm;
    float* sAll = sm + 24576;
    float* bAll = sAll + 96;
    int tid = threadIdx.x;
    const float4* wsrc = (const float4*)g_wAll;
#pragma unroll
    for (int s = 0; s < 24; s++) ((float4*)wAll)[tid + s * 256] = wsrc[tid + s * 256];
    if (tid < 96) {
        sAll[tid] = tid < 32 ? s1[tid] : tid < 64 ? s2[tid - 32] : s3[tid - 64];
        bAll[tid] = tid < 32 ? b1[tid] : tid < 64 ? b2[tid - 32] : b3[tid - 64];
    }
    __syncthreads();
    int gpos = blockIdx.x * 256 + tid;
    int b = gpos >> 12, m = gpos & (N_ - 1);
    const float* xp = x + b * C_ * N_ + m;
    u64 acc2[48];
#pragma unroll
    for (int i = 0; i < 48; i++) acc2[i] = 0ull;
#pragma unroll 2
    for (int k = 0; k < C_; k++) {
        float xv = __ldg(&xp[k * N_]);
        u64 xq = pack2(xv, xv);
        const ulonglong2* wk = (const ulonglong2*)&wAll[k * 96];
#pragma unroll
        for (int t = 0; t < 24; t++) {
            ulonglong2 wv = wk[t];
            acc2[2 * t]     = fma2(xq, wv.x, acc2[2 * t]);
            acc2[2 * t + 1] = fma2(xq, wv.y, acc2[2 * t + 1]);
        }
    }
#pragma unroll
    for (int br = 0; br < 2; br++) {
        unsigned hh[16], ll[16];
        float mulf = br ? L2E : 1.f;
#pragma unroll
        for (int p = 0; p < 16; p++) {
            float v0, v1;
            unpack2(acc2[br * 16 + p], v0, v1);
            float y0 = fmaf(v0, sAll[br * 32 + 2 * p],     bAll[br * 32 + 2 * p]);
            float y1 = fmaf(v1, sAll[br * 32 + 2 * p + 1], bAll[br * 32 + 2 * p + 1]);
            y0 = y0 * frcp(1.f + fexp2(-y0 * L2E)) * mulf;
            y1 = y1 * frcp(1.f + fexp2(-y1 * L2E)) * mulf;
            split2(make_float2(y0, y1), hh[p], ll[p]);
        }
        uint4* d = (uint4*)((br ? g_y2b : g_y1b) + (size_t)gpos * 64);
#pragma unroll
        for (int j = 0; j < 4; j++) d[j]     = make_uint4(hh[4 * j], hh[4 * j + 1], hh[4 * j + 2], hh[4 * j + 3]);
#pragma unroll
        for (int j = 0; j < 4; j++) d[4 + j] = make_uint4(ll[4 * j], ll[4 * j + 1], ll[4 * j + 2], ll[4 * j + 3]);
    }
#pragma unroll
    for (int p = 0; p < 16; p++) {
        float v0, v1;
        unpack2(acc2[32 + p], v0, v1);
        float y0 = fmaf(v0, sAll[64 + 2 * p],     bAll[64 + 2 * p]);
        float y1 = fmaf(v1, sAll[64 + 2 * p + 1], bAll[64 + 2 * p + 1]);
        y0 = y0 * frcp(1.f + fexp2(-y0 * L2E));
        y1 = y1 * frcp(1.f + fexp2(-y1 * L2E));
        size_t base = ((size_t)b * CI + 2 * p) * N_ + m;
        g_y3h[base]      = __float2bfloat16(y0);
        g_y3h[base + N_] = __float2bfloat16(y1);
    }
}

// K2t: softmax stats via mma.sync. grid (32, B, 2), block 128.
__global__ void __launch_bounds__(128) k2t() {
    __shared__ char An[128 * STR + 64 * STR];
    char* Bm = An + 128 * STR;
    u32 sbA = smem_u32(An), sbB = sbA + 128 * STR;
    int tid = threadIdx.x, w = tid >> 5, L = tid & 31;
    int b = blockIdx.y, n0 = blockIdx.x * 128, hz = blockIdx.z;
    {
        const uint4* s = (const uint4*)(g_y2b + ((size_t)b * N_ + n0 + tid) * 64);
        uint4* d = (uint4*)(An + tid * STR);
#pragma unroll
        for (int j = 0; j < 8; j++) d[j] = s[j];
    }
    __syncthreads();
    u32 Ah[2][2][4], Al[2][2][4];
    load_afrags(sbA, w, L, Ah, Al);

    // prefetch tile 0 of y1 m-chunk
    int pr = tid >> 1, ph_ = tid & 1;
    uint4 pf[4];
    {
        const uint4* s = (const uint4*)(g_y1b + ((size_t)b * N_ + hz * 2048 + pr) * 64 + ph_ * 32);
#pragma unroll
        for (int j = 0; j < 4; j++) pf[j] = s[j];
    }

    float M[2][2], Z[2][2];
#pragma unroll
    for (int i = 0; i < 2; i++)
#pragma unroll
        for (int j = 0; j < 2; j++) { M[i][j] = -1.0e30f; Z[i][j] = 0.f; }

    for (int tt = 0; tt < 32; tt++) {
        {
            uint4* d = (uint4*)(Bm + pr * STR + ph_ * 64);
            d[0] = pf[0]; d[1] = pf[1]; d[2] = pf[2]; d[3] = pf[3];
        }
        if (tt < 31) {
            const uint4* s = (const uint4*)(g_y1b + ((size_t)b * N_ + hz * 2048 + (tt + 1) * 64 + pr) * 64 + ph_ * 32);
#pragma unroll
            for (int j = 0; j < 4; j++) pf[j] = s[j];
        }
        __syncthreads();
        float s_[2][8][4];
#pragma unroll
        for (int i = 0; i < 2; i++)
#pragma unroll
            for (int j = 0; j < 8; j++)
#pragma unroll
                for (int q = 0; q < 4; q++) s_[i][j][q] = 0.f;
#pragma unroll
        for (int j = 0; j < 8; j++) {
            u32 bb = sbB + (u32)((j * 8 + (L & 7)) * STR) + (u32)(((L >> 3) & 1) * 16);
            u32 Bh0[2], Bh1[2], Bl0[2], Bl1[2];
            ldsm2(Bh0, bb);      ldsm2(Bh1, bb + 32);
            ldsm2(Bl0, bb + 64); ldsm2(Bl1, bb + 96);
#pragma unroll
            for (int mb = 0; mb < 2; mb++) {
                mma16816(s_[mb][j], Ah[mb][0], Bh0); mma16816(s_[mb][j], Ah[mb][1], Bh1);
                mma16816(s_[mb][j], Al[mb][0], Bh0); mma16816(s_[mb][j], Al[mb][1], Bh1);
                mma16816(s_[mb][j], Ah[mb][0], Bl0); mma16816(s_[mb][j], Ah[mb][1], Bl1);
            }
        }
        __syncthreads();
#pragma unroll
        for (int mb = 0; mb < 2; mb++)
#pragma unroll
            for (int rh = 0; rh < 2; rh++) {
                float mx = -1.0e30f;
#pragma unroll
                for (int j = 0; j < 8; j++)
                    mx = fmaxf(mx, fmaxf(s_[mb][j][rh * 2], s_[mb][j][rh * 2 + 1]));
                float nM = fmaxf(M[mb][rh], mx), ss = 0.f;
#pragma unroll
                for (int j = 0; j < 8; j++)
                    ss += fexp2(s_[mb][j][rh * 2] - nM) + fexp2(s_[mb][j][rh * 2 + 1] - nM);
                Z[mb][rh] = fmaf(Z[mb][rh], fexp2(M[mb][rh] - nM), ss);
                M[mb][rh] = nM;
            }
    }
#pragma unroll
    for (int mb = 0; mb < 2; mb++)
#pragma unroll
        for (int rh = 0; rh < 2; rh++) {
            float m = M[mb][rh], z = Z[mb][rh];
#pragma unroll
            for (int off = 1; off < 4; off <<= 1) {
                float mo = __shfl_xor_sync(0xffffffffu, m, off);
                float zo = __shfl_xor_sync(0xffffffffu, z, off);
                float nM = fmaxf(m, mo);
                z = fmaf(z, fexp2(m - nM), zo * fexp2(mo - nM));
                m = nM;
            }
            if ((L & 3) == 0)
                g_mz[(size_t)(hz * B_ + b) * N_ + n0 + w * 32 + mb * 16 + rh * 8 + (L >> 2)] =
                    make_float2(m, z);
        }
}

__global__ void k2b_merge() {
    int i = blockIdx.x * 256 + threadIdx.x;
    if (i < B_ * N_) {
        float2 a = g_mz[i], c = g_mz[B_ * N_ + i];
        float M = fmaxf(a.x, c.x);
        float Z = a.y * fexp2(a.x - M) + c.y * fexp2(c.x - M);
        g_alpha[i] = M + flog2(Z);
    }
}

// K3t: attention apply via mma.sync + FA2 register P. grid (32, B, 2), block 128.
__global__ void __launch_bounds__(128) k3t() {
    __shared__ char SM[128 * STR + 64 * STR + 32 * STR + 256];
    char* A1 = SM;
    char* Qs = SM + 128 * STR;
    char* Vh = Qs + 64 * STR;
    float* alp = (float*)(Vh + 32 * STR);
    u32 sbA = smem_u32(A1), sbQ = sbA + 128 * STR, sbVh = sbQ + 64 * STR;
    int tid = threadIdx.x, w = tid >> 5, L = tid & 31;
    int b = blockIdx.y, m0 = blockIdx.x * 128, hz = blockIdx.z;
    {
        const uint4* s = (const uint4*)(g_y1b + ((size_t)b * N_ + m0 + tid) * 64);
        uint4* d = (uint4*)(A1 + tid * STR);
#pragma unroll
        for (int j = 0; j < 8; j++) d[j] = s[j];
    }
    __syncthreads();
    u32 Ah[2][2][4], Al[2][2][4];
    load_afrags(sbA, w, L, Ah, Al);

    float d2[2][4][4];
#pragma unroll
    for (int i = 0; i < 2; i++)
#pragma unroll
        for (int j = 0; j < 4; j++)
#pragma unroll
            for (int q = 0; q < 4; q++) d2[i][j][q] = 0.f;

    // prefetch tile 0
    int qr = tid >> 1, qh = tid & 1, vci = tid >> 2, vq = tid & 3;
    uint4 qf[4], vf[2];
    {
        int nc = hz * 2048;
        const uint4* s = (const uint4*)(g_y2b + ((size_t)b * N_ + nc + qr) * 64 + qh * 32);
#pragma unroll
        for (int j = 0; j < 4; j++) qf[j] = s[j];
        const uint4* vh = (const uint4*)(g_y3h + ((size_t)b * CI + vci) * N_ + nc + vq * 16);
        vf[0] = vh[0]; vf[1] = vh[1];
    }

    for (int tt = 0; tt < 32; tt++) {
        int nc = hz * 2048 + tt * 64;
        {
            uint4* d = (uint4*)(Qs + qr * STR + qh * 64);
            d[0] = qf[0]; d[1] = qf[1]; d[2] = qf[2]; d[3] = qf[3];
            uint4* dh = (uint4*)(Vh + vci * STR + vq * 32);
            dh[0] = vf[0]; dh[1] = vf[1];
            if (tid < 16) ((float4*)alp)[tid] = ((const float4*)(g_alpha + (size_t)b * N_ + nc))[tid];
        }
        if (tt < 31) {
            int n1 = nc + 64;
            const uint4* s = (const uint4*)(g_y2b + ((size_t)b * N_ + n1 + qr) * 64 + qh * 32);
#pragma unroll
            for (int j = 0; j < 4; j++) qf[j] = s[j];
            const uint4* vh = (const uint4*)(g_y3h + ((size_t)b * CI + vci) * N_ + n1 + vq * 16);
            vf[0] = vh[0]; vf[1] = vh[1];
        }
        __syncthreads();
#pragma unroll
        for (int nbp = 0; nbp < 4; nbp++) {
            u32 Vhf[4][2];
#pragma unroll
            for (int cb = 0; cb < 4; cb++) {
                u32 va = (u32)((cb * 8 + (L & 7)) * STR) + (u32)(nbp * 32 + ((L >> 3) & 1) * 16);
                ldsm2(Vhf[cb], sbVh + va);
            }
            u32 Bh[2][2][2], Bl[2][2][2];
#pragma unroll
            for (int nb2 = 0; nb2 < 2; nb2++) {
                u32 qa = sbQ + (u32)(((nbp * 2 + nb2) * 8 + (L & 7)) * STR) + (u32)(((L >> 3) & 1) * 16);
                ldsm2(Bh[nb2][0], qa);      ldsm2(Bh[nb2][1], qa + 32);
                ldsm2(Bl[nb2][0], qa + 64); ldsm2(Bl[nb2][1], qa + 96);
            }
#pragma unroll
            for (int mb = 0; mb < 2; mb++) {
                float s_[2][4];
#pragma unroll
                for (int nb2 = 0; nb2 < 2; nb2++) {
#pragma unroll
                    for (int q = 0; q < 4; q++) s_[nb2][q] = 0.f;
                    mma16816(s_[nb2], Ah[mb][0], Bh[nb2][0]); mma16816(s_[nb2], Ah[mb][1], Bh[nb2][1]);
                    mma16816(s_[nb2], Al[mb][0], Bh[nb2][0]); mma16816(s_[nb2], Al[mb][1], Bh[nb2][1]);
                    mma16816(s_[nb2], Ah[mb][0], Bl[nb2][0]); mma16816(s_[nb2], Ah[mb][1], Bl[nb2][1]);
                }
                u32 ph[4], pl[4];
#pragma unroll
                for (int nb2 = 0; nb2 < 2; nb2++) {
                    int cn = (nbp * 2 + nb2) * 8 + 2 * (L & 3);
                    float a0 = alp[cn], a1 = alp[cn + 1];
                    float e0 = fexp2(s_[nb2][0] - a0), e1 = fexp2(s_[nb2][1] - a1);
                    float e2 = fexp2(s_[nb2][2] - a0), e3 = fexp2(s_[nb2][3] - a1);
                    u32 h01 = cvt2(e0, e1), h23 = cvt2(e2, e3);
                    ph[nb2 * 2] = h01; ph[nb2 * 2 + 1] = h23;
                    pl[nb2 * 2]     = cvt2(e0 - lo_f(h01), e1 - hi_f(h01));
                    pl[nb2 * 2 + 1] = cvt2(e2 - lo_f(h23), e3 - hi_f(h23));
                }
#pragma unroll
                for (int cb = 0; cb < 4; cb++) {
                    mma16816(d2[mb][cb], ph, Vhf[cb]);
                    mma16816(d2[mb][cb], pl, Vhf[cb]);
                }
            }
        }
        __syncthreads();
    }
    float* pp = g_part + (size_t)(hz * B_ + b) * CI * N_;
#pragma unroll
    for (int mb = 0; mb < 2; mb++)
#pragma unroll
        for (int cb = 0; cb < 4; cb++) {
            int row = m0 + w * 32 + mb * 16 + (L >> 2);
            int ci0 = cb * 8 + 2 * (L & 3);
            pp[(size_t)ci0 * N_ + row]           = d2[mb][cb][0];
            pp[(size_t)(ci0 + 1) * N_ + row]     = d2[mb][cb][1];
            pp[(size_t)ci0 * N_ + row + 8]       = d2[mb][cb][2];
            pp[(size_t)(ci0 + 1) * N_ + row + 8] = d2[mb][cb][3];
        }
}

// K4: reduce 2 partials + final conv + BN + SiLU + residual. grid (64,8), block 128
__global__ void __launch_bounds__(128) k4_epi(
    const float* __restrict__ w4, const float* __restrict__ s4,
    const float* __restrict__ b4, const float* __restrict__ x,
    float* __restrict__ out) {
    __shared__ float Ys[32 * 68];
    __shared__ float W4t[32 * 260];
    __shared__ float s4s[256], b4s[256];
    int b = blockIdx.y, m0 = blockIdx.x * 64;
    int tid = threadIdx.x;
    int mg = tid & 15, cg = tid >> 4;
    const float* q0 = g_part + (size_t)b * CI * N_;
    const float* q1 = g_part + (size_t)(B_ + b) * CI * N_;
#pragma unroll
    for (int s = 0; s < 4; s++) {
        int idx = tid + s * 128;
        int ci = idx >> 4, off = (idx & 15) << 2;
        float4 u = *(const float4*)&q0[ci * N_ + m0 + off];
        float4 v = *(const float4*)&q1[ci * N_ + m0 + off];
        u.x += v.x; u.y += v.y; u.z += v.z; u.w += v.w;
        *(float4*)&Ys[ci * 68 + off] = u;
    }
    for (int idx = tid; idx < C_ * CI; idx += 128) {
        int co = idx >> 5, k = idx & 31;
        W4t[k * 260 + co] = w4[idx];
    }
    s4s[tid] = s4[tid]; s4s[tid + 128] = s4[tid + 128];
    b4s[tid] = b4[tid]; b4s[tid + 128] = b4[tid + 128];
    __syncthreads();
#pragma unroll
    for (int pass = 0; pass < 2; pass++) {
        int co0 = cg * 16 + pass * 128;
        u64 e2[16][2];
#pragma unroll
        for (int j = 0; j < 16; j++) { e2[j][0] = 0ull; e2[j][1] = 0ull; }
#pragma unroll 4
        for (int k = 0; k < CI; k++) {
            ulonglong2 ym = *(const ulonglong2*)&Ys[k * 68 + mg * 4];
#pragma unroll
            for (int q = 0; q < 4; q++) {
                float4 wq = *(const float4*)&W4t[k * 260 + co0 + q * 4];
                u64 w0 = pack2(wq.x, wq.x), w1 = pack2(wq.y, wq.y);
                u64 w2 = pack2(wq.z, wq.z), w3 = pack2(wq.w, wq.w);
                e2[q * 4 + 0][0] = fma2(w0, ym.x, e2[q * 4 + 0][0]);
                e2[q * 4 + 0][1] = fma2(w0, ym.y, e2[q * 4 + 0][1]);
                e2[q * 4 + 1][0] = fma2(w1, ym.x, e2[q * 4 + 1][0]);
                e2[q * 4 + 1][1] = fma2(w1, ym.y, e2[q * 4 + 1][1]);
                e2[q * 4 + 2][0] = fma2(w2, ym.x, e2[q * 4 + 2][0]);
                e2[q * 4 + 2][1] = fma2(w2, ym.y, e2[q * 4 + 2][1]);
                e2[q * 4 + 3][0] = fma2(w3, ym.x, e2[q * 4 + 3][0]);
                e2[q * 4 + 3][1] = fma2(w3, ym.y, e2[q * 4 + 3][1]);
            }
        }
#pragma unroll
        for (int j = 0; j < 16; j++) {
            int co = co0 + j;
            float sc = s4s[co], bi = b4s[co];
            float v0, v1, v2, v3;
            unpack2(e2[j][0], v0, v1); unpack2(e2[j][1], v2, v3);
            float y0 = fmaf(v0, sc, bi), y1 = fmaf(v1, sc, bi);
            float y2v = fmaf(v2, sc, bi), y3v = fmaf(v3, sc, bi);
            int off = b * C_ * N_ + co * N_ + m0 + mg * 4;
            float4 xr = *(const float4*)&x[off];
            float4 ov;
            ov.x = fmaf(y0,  frcp(1.f + fexp2(-y0 * L2E)),  xr.x);
            ov.y = fmaf(y1,  frcp(1.f + fexp2(-y1 * L2E)),  xr.y);
            ov.z = fmaf(y2v, frcp(1.f + fexp2(-y2v * L2E)), xr.z);
            ov.w = fmaf(y3v, frcp(1.f + fexp2(-y3v * L2E)), xr.w);
            *(float4*)&out[off] = ov;
        }
    }
}

extern "C" void kernel_launch(void* const* d_in, const int* in_sizes, int n_in,
                              void* d_out, int out_size) {
    (void)in_sizes; (void)n_in; (void)out_size;
    const float* x  = (const float*)d_in[0];
    const float* w1 = (const float*)d_in[1];
    const float* s1 = (const float*)d_in[2];
    const float* b1 = (const float*)d_in[3];
    const float* w2 = (const float*)d_in[4];
    const float* s2 = (const float*)d_in[5];
    const float* b2 = (const float*)d_in[6];
    const float* w3 = (const float*)d_in[7];
    const float* s3 = (const float*)d_in[8];
    const float* b3 = (const float*)d_in[9];
    const float* w4 = (const float*)d_in[10];
    const float* s4 = (const float*)d_in[11];
    const float* b4 = (const float*)d_in[12];
    float* out = (float*)d_out;

    cudaFuncSetAttribute(k1_conv, cudaFuncAttributeMaxDynamicSharedMemorySize, 99072);

    k0_prep<<<96, 256>>>(w1, w2, w3);
    k1_conv<<<128, 256, 99072>>>(x, s1, b1, s2, b2, s3, b3);
    k2t<<<dim3(32, B_, 2), 128>>>();
    k2b_merge<<<(B_ * N_ + 255) / 256, 256>>>();
    k3t<<<dim3(32, B_, 2), 128>>>();
    k4_epi<<<dim3(64, B_), 128>>>(w4, s4, b4, x, out);
}

// round 12
// speedup vs baseline: 4.1885x; 1.0629x over previous
#include <cuda_runtime.h>
#include <cuda_bf16.h>
#include <cstdint>

#define DEV_INLINE __device__ __forceinline__
typedef unsigned long long u64;
typedef uint32_t u32;

constexpr int B_ = 8;
constexpr int C_ = 256;
constexpr int CI = 32;
constexpr int N_ = 4096;
constexpr int NSPL = 4;                  // split factor for k2/k3
constexpr float L2E = 1.4426950408889634f;
constexpr int STR = 144;                 // smem operand row stride (bytes)

__device__ __align__(128) float g_alpha[B_ * N_];
__device__ __align__(128) float g_wAll[C_ * 96];
__device__ __align__(128) float g_part[NSPL * B_ * CI * N_];
__device__ __align__(128) float2 g_mz[NSPL * B_ * N_];
__device__ __align__(128) __nv_bfloat16 g_y1b[(size_t)B_ * N_ * 64];  // [pos][32hi|32lo]
__device__ __align__(128) __nv_bfloat16 g_y2b[(size_t)B_ * N_ * 64];  // pre-scaled log2e
__device__ __align__(128) __nv_bfloat16 g_y3h[(size_t)B_ * CI * N_];  // [ci][n] hi

DEV_INLINE float fexp2(float v) { float y; asm("ex2.approx.ftz.f32 %0, %1;" : "=f"(y) : "f"(v)); return y; }
DEV_INLINE float flog2(float v) { float y; asm("lg2.approx.ftz.f32 %0, %1;" : "=f"(y) : "f"(v)); return y; }
DEV_INLINE float frcp(float v)  { float y; asm("rcp.approx.ftz.f32 %0, %1;" : "=f"(y) : "f"(v)); return y; }
DEV_INLINE u64 pack2(float lo, float hi) {
    u64 r; asm("mov.b64 %0, {%1,%2};" : "=l"(r) : "r"(__float_as_uint(lo)), "r"(__float_as_uint(hi)));
    return r;
}
DEV_INLINE void unpack2(u64 v, float& lo, float& hi) {
    unsigned a, b; asm("mov.b64 {%0,%1}, %2;" : "=r"(a), "=r"(b) : "l"(v));
    lo = __uint_as_float(a); hi = __uint_as_float(b);
}
DEV_INLINE u64 fma2(u64 a, u64 b, u64 c) {
    u64 d; asm("fma.rn.f32x2 %0, %1, %2, %3;" : "=l"(d) : "l"(a), "l"(b), "l"(c));
    return d;
}
DEV_INLINE void split2(float2 f, unsigned& h, unsigned& l) {
    __nv_bfloat162 hb = __float22bfloat162_rn(f);
    h = *(unsigned*)&hb;
    float2 hf = __bfloat1622float2(hb);
    __nv_bfloat162 lb = __float22bfloat162_rn(make_float2(f.x - hf.x, f.y - hf.y));
    l = *(unsigned*)&lb;
}
DEV_INLINE u32 smem_u32(const void* p) {
    u32 a; asm("{ .reg .u64 t; cvta.to.shared.u64 t, %1; cvt.u32.u64 %0, t; }" : "=r"(a) : "l"(p));
    return a;
}
DEV_INLINE void ldsm4(u32* r, u32 a) {
    asm volatile("ldmatrix.sync.aligned.m8n8.x4.shared.b16 {%0,%1,%2,%3}, [%4];"
                 : "=r"(r[0]), "=r"(r[1]), "=r"(r[2]), "=r"(r[3]) : "r"(a));
}
DEV_INLINE void ldsm2(u32* r, u32 a) {
    asm volatile("ldmatrix.sync.aligned.m8n8.x2.shared.b16 {%0,%1}, [%2];"
                 : "=r"(r[0]), "=r"(r[1]) : "r"(a));
}
DEV_INLINE void mma16816(float* d, const u32* a, const u32* b) {
    asm volatile("mma.sync.aligned.m16n8k16.row.col.f32.bf16.bf16.f32 "
        "{%0,%1,%2,%3},{%4,%5,%6,%7},{%8,%9},{%0,%1,%2,%3};"
        : "+f"(d[0]), "+f"(d[1]), "+f"(d[2]), "+f"(d[3])
        : "r"(a[0]), "r"(a[1]), "r"(a[2]), "r"(a[3]), "r"(b[0]), "r"(b[1]));
}
DEV_INLINE u32 cvt2(float lo, float hi) {
    u32 r; asm("cvt.rn.bf16x2.f32 %0, %1, %2;" : "=r"(r) : "f"(hi), "f"(lo));
    return r;
}
DEV_INLINE float lo_f(u32 h) { return __uint_as_float(h << 16); }
DEV_INLINE float hi_f(u32 h) { return __uint_as_float(h & 0xffff0000u); }

DEV_INLINE void load_afrags(u32 base, int w, int L, u32 Ah[2][2][4], u32 Al[2][2][4]) {
#pragma unroll
    for (int mb = 0; mb < 2; mb++) {
        u32 a = base + (u32)((w * 32 + mb * 16 + (L & 15)) * STR) + (u32)((L >> 4) * 16);
#pragma unroll
        for (int k = 0; k < 2; k++) {
            ldsm4(Ah[mb][k], a + k * 32);
            ldsm4(Al[mb][k], a + 64 + k * 32);
        }
    }
}

// ---------------------------------------------------------------------------
__global__ void k0_prep(const float* __restrict__ w1, const float* __restrict__ w2,
                        const float* __restrict__ w3) {
    int i = blockIdx.x * 256 + threadIdx.x;
    if (i < C_ * 96) {
        int k = i / 96, j = i - k * 96;
        int br = j >> 5, co = j & 31;
        const float* w = br == 0 ? w1 : br == 1 ? w2 : w3;
        g_wAll[i] = w[co * C_ + k];
    }
}

// K1: three branch convs fused; emits bf16 split operands. grid 128, block 256.
__global__ void __launch_bounds__(256, 1) k1_conv(
    const float* __restrict__ x,
    const float* __restrict__ s1, const float* __restrict__ b1,
    const float* __restrict__ s2, const float* __restrict__ b2,
    const float* __restrict__ s3, const float* __restrict__ b3) {
    extern __shared__ float sm[];
    float* wAll = sm;
    float* sAll = sm + 24576;
    float* bAll = sAll + 96;
    int tid = threadIdx.x;
    const float4* wsrc = (const float4*)g_wAll;
#pragma unroll
    for (int s = 0; s < 24; s++) ((float4*)wAll)[tid + s * 256] = wsrc[tid + s * 256];
    if (tid < 96) {
        sAll[tid] = tid < 32 ? s1[tid] : tid < 64 ? s2[tid - 32] : s3[tid - 64];
        bAll[tid] = tid < 32 ? b1[tid] : tid < 64 ? b2[tid - 32] : b3[tid - 64];
    }
    __syncthreads();
    int gpos = blockIdx.x * 256 + tid;
    int b = gpos >> 12, m = gpos & (N_ - 1);
    const float* xp = x + b * C_ * N_ + m;
    u64 acc2[48];
#pragma unroll
    for (int i = 0; i < 48; i++) acc2[i] = 0ull;
#pragma unroll 2
    for (int k = 0; k < C_; k++) {
        float xv = __ldg(&xp[k * N_]);
        u64 xq = pack2(xv, xv);
        const ulonglong2* wk = (const ulonglong2*)&wAll[k * 96];
#pragma unroll
        for (int t = 0; t < 24; t++) {
            ulonglong2 wv = wk[t];
            acc2[2 * t]     = fma2(xq, wv.x, acc2[2 * t]);
            acc2[2 * t + 1] = fma2(xq, wv.y, acc2[2 * t + 1]);
        }
    }
#pragma unroll
    for (int br = 0; br < 2; br++) {
        unsigned hh[16], ll[16];
        float mulf = br ? L2E : 1.f;
#pragma unroll
        for (int p = 0; p < 16; p++) {
            float v0, v1;
            unpack2(acc2[br * 16 + p], v0, v1);
            float y0 = fmaf(v0, sAll[br * 32 + 2 * p],     bAll[br * 32 + 2 * p]);
            float y1 = fmaf(v1, sAll[br * 32 + 2 * p + 1], bAll[br * 32 + 2 * p + 1]);
            y0 = y0 * frcp(1.f + fexp2(-y0 * L2E)) * mulf;
            y1 = y1 * frcp(1.f + fexp2(-y1 * L2E)) * mulf;
            split2(make_float2(y0, y1), hh[p], ll[p]);
        }
        uint4* d = (uint4*)((br ? g_y2b : g_y1b) + (size_t)gpos * 64);
#pragma unroll
        for (int j = 0; j < 4; j++) d[j]     = make_uint4(hh[4 * j], hh[4 * j + 1], hh[4 * j + 2], hh[4 * j + 3]);
#pragma unroll
        for (int j = 0; j < 4; j++) d[4 + j] = make_uint4(ll[4 * j], ll[4 * j + 1], ll[4 * j + 2], ll[4 * j + 3]);
    }
#pragma unroll
    for (int p = 0; p < 16; p++) {
        float v0, v1;
        unpack2(acc2[32 + p], v0, v1);
        float y0 = fmaf(v0, sAll[64 + 2 * p],     bAll[64 + 2 * p]);
        float y1 = fmaf(v1, sAll[64 + 2 * p + 1], bAll[64 + 2 * p + 1]);
        y0 = y0 * frcp(1.f + fexp2(-y0 * L2E));
        y1 = y1 * frcp(1.f + fexp2(-y1 * L2E));
        size_t base = ((size_t)b * CI + 2 * p) * N_ + m;
        g_y3h[base]      = __float2bfloat16(y0);
        g_y3h[base + N_] = __float2bfloat16(y1);
    }
}

// K2t: softmax stats via mma.sync, ping-pong B. grid (32, B, NSPL), block 128.
__global__ void __launch_bounds__(128) k2t() {
    __shared__ char SM[128 * STR + 2 * 64 * STR];
    char* An = SM;
    u32 sbA = smem_u32(An), sbB0 = sbA + 128 * STR;
    int tid = threadIdx.x, w = tid >> 5, L = tid & 31;
    int b = blockIdx.y, n0 = blockIdx.x * 128, hz = blockIdx.z;
    int mbase0 = hz * (N_ / NSPL);
    constexpr int NT = N_ / NSPL / 64;   // 16 tiles
    {
        const uint4* s = (const uint4*)(g_y2b + ((size_t)b * N_ + n0 + tid) * 64);
        uint4* d = (uint4*)(An + tid * STR);
#pragma unroll
        for (int j = 0; j < 8; j++) d[j] = s[j];
    }
    __syncthreads();
    u32 Ah[2][2][4], Al[2][2][4];
    load_afrags(sbA, w, L, Ah, Al);

    int pr = tid >> 1, ph_ = tid & 1;
    uint4 pf[4];
    {
        const uint4* s = (const uint4*)(g_y1b + ((size_t)b * N_ + mbase0 + pr) * 64 + ph_ * 32);
#pragma unroll
        for (int j = 0; j < 4; j++) pf[j] = s[j];
    }

    float M[2][2], Z[2][2];
#pragma unroll
    for (int i = 0; i < 2; i++)
#pragma unroll
        for (int j = 0; j < 2; j++) { M[i][j] = -1.0e30f; Z[i][j] = 0.f; }

    for (int tt = 0; tt < NT; tt++) {
        u32 sbB = sbB0 + (u32)((tt & 1) * 64 * STR);
        {
            uint4* d = (uint4*)(SM + 128 * STR + (tt & 1) * 64 * STR + pr * STR + ph_ * 64);
            d[0] = pf[0]; d[1] = pf[1]; d[2] = pf[2]; d[3] = pf[3];
        }
        if (tt < NT - 1) {
            const uint4* s = (const uint4*)(g_y1b + ((size_t)b * N_ + mbase0 + (tt + 1) * 64 + pr) * 64 + ph_ * 32);
#pragma unroll
            for (int j = 0; j < 4; j++) pf[j] = s[j];
        }
        __syncthreads();
        float s_[2][8][4];
#pragma unroll
        for (int i = 0; i < 2; i++)
#pragma unroll
            for (int j = 0; j < 8; j++)
#pragma unroll
                for (int q = 0; q < 4; q++) s_[i][j][q] = 0.f;
#pragma unroll
        for (int j = 0; j < 8; j++) {
            u32 bb = sbB + (u32)((j * 8 + (L & 7)) * STR) + (u32)(((L >> 3) & 1) * 16);
            u32 Bh0[2], Bh1[2], Bl0[2], Bl1[2];
            ldsm2(Bh0, bb);      ldsm2(Bh1, bb + 32);
            ldsm2(Bl0, bb + 64); ldsm2(Bl1, bb + 96);
#pragma unroll
            for (int mb = 0; mb < 2; mb++) {
                mma16816(s_[mb][j], Ah[mb][0], Bh0); mma16816(s_[mb][j], Ah[mb][1], Bh1);
                mma16816(s_[mb][j], Al[mb][0], Bh0); mma16816(s_[mb][j], Al[mb][1], Bh1);
                mma16816(s_[mb][j], Ah[mb][0], Bl0); mma16816(s_[mb][j], Ah[mb][1], Bl1);
            }
        }
#pragma unroll
        for (int mb = 0; mb < 2; mb++)
#pragma unroll
            for (int rh = 0; rh < 2; rh++) {
                float mx = -1.0e30f;
#pragma unroll
                for (int j = 0; j < 8; j++)
                    mx = fmaxf(mx, fmaxf(s_[mb][j][rh * 2], s_[mb][j][rh * 2 + 1]));
                float nM = fmaxf(M[mb][rh], mx), ss = 0.f;
#pragma unroll
                for (int j = 0; j < 8; j++)
                    ss += fexp2(s_[mb][j][rh * 2] - nM) + fexp2(s_[mb][j][rh * 2 + 1] - nM);
                Z[mb][rh] = fmaf(Z[mb][rh], fexp2(M[mb][rh] - nM), ss);
                M[mb][rh] = nM;
            }
    }
#pragma unroll
    for (int mb = 0; mb < 2; mb++)
#pragma unroll
        for (int rh = 0; rh < 2; rh++) {
            float m = M[mb][rh], z = Z[mb][rh];
#pragma unroll
            for (int off = 1; off < 4; off <<= 1) {
                float mo = __shfl_xor_sync(0xffffffffu, m, off);
                float zo = __shfl_xor_sync(0xffffffffu, z, off);
                float nM = fmaxf(m, mo);
                z = fmaf(z, fexp2(m - nM), zo * fexp2(mo - nM));
                m = nM;
            }
            if ((L & 3) == 0)
                g_mz[(size_t)(hz * B_ + b) * N_ + n0 + w * 32 + mb * 16 + rh * 8 + (L >> 2)] =
                    make_float2(m, z);
        }
}

__global__ void k2b_merge() {
    int i = blockIdx.x * 256 + threadIdx.x;
    if (i < B_ * N_) {
        float2 p0 = g_mz[i];
        float2 p1 = g_mz[B_ * N_ + i];
        float2 p2 = g_mz[2 * B_ * N_ + i];
        float2 p3 = g_mz[3 * B_ * N_ + i];
        float M = fmaxf(fmaxf(p0.x, p1.x), fmaxf(p2.x, p3.x));
        float Z = p0.y * fexp2(p0.x - M) + p1.y * fexp2(p1.x - M)
                + p2.y * fexp2(p2.x - M) + p3.y * fexp2(p3.x - M);
        g_alpha[i] = M + flog2(Z);
    }
}

// K3t: attention apply via mma.sync + FA2 register P, ping-pong Q/V/alpha.
// grid (32, B, NSPL), block 128.
__global__ void __launch_bounds__(128) k3t() {
    __shared__ char SM[128 * STR + 2 * 64 * STR + 2 * 32 * STR + 2 * 256 + 128];
    char* A1 = SM;
    const int QOFF = 128 * STR;
    const int VOFF = QOFF + 2 * 64 * STR;
    const int AOFF = VOFF + 2 * 32 * STR;
    u32 sbA = smem_u32(A1);
    int tid = threadIdx.x, w = tid >> 5, L = tid & 31;
    int b = blockIdx.y, m0 = blockIdx.x * 128, hz = blockIdx.z;
    int nbase0 = hz * (N_ / NSPL);
    constexpr int NT = N_ / NSPL / 64;
    {
        const uint4* s = (const uint4*)(g_y1b + ((size_t)b * N_ + m0 + tid) * 64);
        uint4* d = (uint4*)(A1 + tid * STR);
#pragma unroll
        for (int j = 0; j < 8; j++) d[j] = s[j];
    }
    __syncthreads();
    u32 Ah[2][2][4], Al[2][2][4];
    load_afrags(sbA, w, L, Ah, Al);

    float d2[2][4][4];
#pragma unroll
    for (int i = 0; i < 2; i++)
#pragma unroll
        for (int j = 0; j < 4; j++)
#pragma unroll
            for (int q = 0; q < 4; q++) d2[i][j][q] = 0.f;

    int qr = tid >> 1, qh = tid & 1, vci = tid >> 2, vq = tid & 3;
    uint4 qf[4], vf[2];
    {
        const uint4* s = (const uint4*)(g_y2b + ((size_t)b * N_ + nbase0 + qr) * 64 + qh * 32);
#pragma unroll
        for (int j = 0; j < 4; j++) qf[j] = s[j];
        const uint4* vh = (const uint4*)(g_y3h + ((size_t)b * CI + vci) * N_ + nbase0 + vq * 16);
        vf[0] = vh[0]; vf[1] = vh[1];
    }

    for (int tt = 0; tt < NT; tt++) {
        int cur = tt & 1;
        u32 sbQ = sbA + (u32)(QOFF + cur * 64 * STR);
        u32 sbVh = sbA + (u32)(VOFF + cur * 32 * STR);
        float* alp = (float*)(SM + AOFF + cur * 256);
        {
            uint4* d = (uint4*)(SM + QOFF + cur * 64 * STR + qr * STR + qh * 64);
            d[0] = qf[0]; d[1] = qf[1]; d[2] = qf[2]; d[3] = qf[3];
            uint4* dh = (uint4*)(SM + VOFF + cur * 32 * STR + vci * STR + vq * 32);
            dh[0] = vf[0]; dh[1] = vf[1];
            if (tid < 16)
                ((float4*)alp)[tid] = ((const float4*)(g_alpha + (size_t)b * N_ + nbase0 + tt * 64))[tid];
        }
        if (tt < NT - 1) {
            int n1 = nbase0 + (tt + 1) * 64;
            const uint4* s = (const uint4*)(g_y2b + ((size_t)b * N_ + n1 + qr) * 64 + qh * 32);
#pragma unroll
            for (int j = 0; j < 4; j++) qf[j] = s[j];
            const uint4* vh = (const uint4*)(g_y3h + ((size_t)b * CI + vci) * N_ + n1 + vq * 16);
            vf[0] = vh[0]; vf[1] = vh[1];
        }
        __syncthreads();
#pragma unroll
        for (int nbp = 0; nbp < 4; nbp++) {
            u32 Vhf[4][2];
#pragma unroll
            for (int cb = 0; cb < 4; cb++) {
                u32 va = (u32)((cb * 8 + (L & 7)) * STR) + (u32)(nbp * 32 + ((L >> 3) & 1) * 16);
                ldsm2(Vhf[cb], sbVh + va);
            }
            u32 Bh[2][2][2], Bl[2][2][2];
#pragma unroll
            for (int nb2 = 0; nb2 < 2; nb2++) {
                u32 qa = sbQ + (u32)(((nbp * 2 + nb2) * 8 + (L & 7)) * STR) + (u32)(((L >> 3) & 1) * 16);
                ldsm2(Bh[nb2][0], qa);      ldsm2(Bh[nb2][1], qa + 32);
                ldsm2(Bl[nb2][0], qa + 64); ldsm2(Bl[nb2][1], qa + 96);
            }
#pragma unroll
            for (int mb = 0; mb < 2; mb++) {
                float s_[2][4];
#pragma unroll
                for (int nb2 = 0; nb2 < 2; nb2++) {
#pragma unroll
                    for (int q = 0; q < 4; q++) s_[nb2][q] = 0.f;
                    mma16816(s_[nb2], Ah[mb][0], Bh[nb2][0]); mma16816(s_[nb2], Ah[mb][1], Bh[nb2][1]);
                    mma16816(s_[nb2], Al[mb][0], Bh[nb2][0]); mma16816(s_[nb2], Al[mb][1], Bh[nb2][1]);
                    mma16816(s_[nb2], Ah[mb][0], Bl[nb2][0]); mma16816(s_[nb2], Ah[mb][1], Bl[nb2][1]);
                }
                u32 ph[4], pl[4];
#pragma unroll
                for (int nb2 = 0; nb2 < 2; nb2++) {
                    int cn = (nbp * 2 + nb2) * 8 + 2 * (L & 3);
                    float a0 = alp[cn], a1 = alp[cn + 1];
                    float e0 = fexp2(s_[nb2][0] - a0), e1 = fexp2(s_[nb2][1] - a1);
                    float e2 = fexp2(s_[nb2][2] - a0), e3 = fexp2(s_[nb2][3] - a1);
                    u32 h01 = cvt2(e0, e1), h23 = cvt2(e2, e3);
                    ph[nb2 * 2] = h01; ph[nb2 * 2 + 1] = h23;
                    pl[nb2 * 2]     = cvt2(e0 - lo_f(h01), e1 - hi_f(h01));
                    pl[nb2 * 2 + 1] = cvt2(e2 - lo_f(h23), e3 - hi_f(h23));
                }
#pragma unroll
                for (int cb = 0; cb < 4; cb++) {
                    mma16816(d2[mb][cb], ph, Vhf[cb]);
                    mma16816(d2[mb][cb], pl, Vhf[cb]);
                }
            }
        }
    }
    float* pp = g_part + (size_t)(hz * B_ + b) * CI * N_;
#pragma unroll
    for (int mb = 0; mb < 2; mb++)
#pragma unroll
        for (int cb = 0; cb < 4; cb++) {
            int row = m0 + w * 32 + mb * 16 + (L >> 2);
            int ci0 = cb * 8 + 2 * (L & 3);
            pp[(size_t)ci0 * N_ + row]           = d2[mb][cb][0];
            pp[(size_t)(ci0 + 1) * N_ + row]     = d2[mb][cb][1];
            pp[(size_t)ci0 * N_ + row + 8]       = d2[mb][cb][2];
            pp[(size_t)(ci0 + 1) * N_ + row + 8] = d2[mb][cb][3];
        }
}

// K4: reduce NSPL partials + final conv + BN + SiLU + residual. grid (64,8), block 128
__global__ void __launch_bounds__(128) k4_epi(
    const float* __restrict__ w4, const float* __restrict__ s4,
    const float* __restrict__ b4, const float* __restrict__ x,
    float* __restrict__ out) {
    __shared__ float Ys[32 * 68];
    __shared__ float W4t[32 * 260];
    __shared__ float s4s[256], b4s[256];
    int b = blockIdx.y, m0 = blockIdx.x * 64;
    int tid = threadIdx.x;
    int mg = tid & 15, cg = tid >> 4;
#pragma unroll
    for (int s = 0; s < 4; s++) {
        int idx = tid + s * 128;
        int ci = idx >> 4, off = (idx & 15) << 2;
        float4 u = make_float4(0.f, 0.f, 0.f, 0.f);
#pragma unroll
        for (int hz = 0; hz < NSPL; hz++) {
            const float4 v = *(const float4*)&g_part[(size_t)(hz * B_ + b) * CI * N_ + ci * N_ + m0 + off];
            u.x += v.x; u.y += v.y; u.z += v.z; u.w += v.w;
        }
        *(float4*)&Ys[ci * 68 + off] = u;
    }
    for (int idx = tid; idx < C_ * CI; idx += 128) {
        int co = idx >> 5, k = idx & 31;
        W4t[k * 260 + co] = w4[idx];
    }
    s4s[tid] = s4[tid]; s4s[tid + 128] = s4[tid + 128];
    b4s[tid] = b4[tid]; b4s[tid + 128] = b4[tid + 128];
    __syncthreads();
#pragma unroll
    for (int pass = 0; pass < 2; pass++) {
        int co0 = cg * 16 + pass * 128;
        u64 e2[16][2];
#pragma unroll
        for (int j = 0; j < 16; j++) { e2[j][0] = 0ull; e2[j][1] = 0ull; }
#pragma unroll 4
        for (int k = 0; k < CI; k++) {
            ulonglong2 ym = *(const ulonglong2*)&Ys[k * 68 + mg * 4];
#pragma unroll
            for (int q = 0; q < 4; q++) {
                float4 wq = *(const float4*)&W4t[k * 260 + co0 + q * 4];
                u64 w0 = pack2(wq.x, wq.x), w1 = pack2(wq.y, wq.y);
                u64 w2 = pack2(wq.z, wq.z), w3 = pack2(wq.w, wq.w);
                e2[q * 4 + 0][0] = fma2(w0, ym.x, e2[q * 4 + 0][0]);
                e2[q * 4 + 0][1] = fma2(w0, ym.y, e2[q * 4 + 0][1]);
                e2[q * 4 + 1][0] = fma2(w1, ym.x, e2[q * 4 + 1][0]);
                e2[q * 4 + 1][1] = fma2(w1, ym.y, e2[q * 4 + 1][1]);
                e2[q * 4 + 2][0] = fma2(w2, ym.x, e2[q * 4 + 2][0]);
                e2[q * 4 + 2][1] = fma2(w2, ym.y, e2[q * 4 + 2][1]);
                e2[q * 4 + 3][0] = fma2(w3, ym.x, e2[q * 4 + 3][0]);
                e2[q * 4 + 3][1] = fma2(w3, ym.y, e2[q * 4 + 3][1]);
            }
        }
#pragma unroll
        for (int j = 0; j < 16; j++) {
            int co = co0 + j;
            float sc = s4s[co], bi = b4s[co];
            float v0, v1, v2, v3;
            unpack2(e2[j][0], v0, v1); unpack2(e2[j][1], v2, v3);
            float y0 = fmaf(v0, sc, bi), y1 = fmaf(v1, sc, bi);
            float y2v = fmaf(v2, sc, bi), y3v = fmaf(v3, sc, bi);
            int off = b * C_ * N_ + co * N_ + m0 + mg * 4;
            float4 xr = *(const float4*)&x[off];
            float4 ov;
            ov.x = fmaf(y0,  frcp(1.f + fexp2(-y0 * L2E)),  xr.x);
            ov.y = fmaf(y1,  frcp(1.f + fexp2(-y1 * L2E)),  xr.y);
            ov.z = fmaf(y2v, frcp(1.f + fexp2(-y2v * L2E)), xr.z);
            ov.w = fmaf(y3v, frcp(1.f + fexp2(-y3v * L2E)), xr.w);
            *(float4*)&out[off] = ov;
        }
    }
}

extern "C" void kernel_launch(void* const* d_in, const int* in_sizes, int n_in,
                              void* d_out, int out_size) {
    (void)in_sizes; (void)n_in; (void)out_size;
    const float* x  = (const float*)d_in[0];
    const float* w1 = (const float*)d_in[1];
    const float* s1 = (const float*)d_in[2];
    const float* b1 = (const float*)d_in[3];
    const float* w2 = (const float*)d_in[4];
    const float* s2 = (const float*)d_in[5];
    const float* b2 = (const float*)d_in[6];
    const float* w3 = (const float*)d_in[7];
    const float* s3 = (const float*)d_in[8];
    const float* b3 = (const float*)d_in[9];
    const float* w4 = (const float*)d_in[10];
    const float* s4 = (const float*)d_in[11];
    const float* b4 = (const float*)d_in[12];
    float* out = (float*)d_out;

    cudaFuncSetAttribute(k1_conv, cudaFuncAttributeMaxDynamicSharedMemorySize, 99072);

    k0_prep<<<96, 256>>>(w1, w2, w3);
    k1_conv<<<128, 256, 99072>>>(x, s1, b1, s2, b2, s3, b3);
    k2t<<<dim3(32, B_, NSPL), 128>>>();
    k2b_merge<<<(B_ * N_ + 255) / 256, 256>>>();
    k3t<<<dim3(32, B_, NSPL), 128>>>();
    k4_epi<<<dim3(64, B_), 128>>>(w4, s4, b4, x, out);
}